// round 6
// baseline (speedup 1.0000x reference)
#include <cuda_runtime.h>
#include <math.h>

#define Bz  48
#define Ez  512
#define Hz  1024
#define Vz  32000
#define Tz  64
#define G3  3072            // 3*H
#define EP1 513             // E+1
#define OPLD 520            // padded ld for o partials (520*4B % 16 == 0)
#define BTV (Bz*Tz*Vz)      // 98,304,000
#define NPART 12            // gate split-K parts: 4 for ig (K=128 ea), 8 for hg (K=128 ea)

// ---------------- scratch (static device memory, no allocation) ----------------
__device__ float g_emb[Tz * Bz * Ez];        // emb_t for t=0..63   (6.29 MB)
__device__ float g_h[2][Bz * Hz];            // hidden ping-pong
__device__ float g_peep[Bz * G3];            // latent @ Wp^T + bp  (constant over t)
__device__ float g_gpart[NPART][Bz * G3];    // split-K gate partials (7.1 MB)
__device__ float g_opart[8 * Bz * OPLD];     // split-K partials for o

__device__ __forceinline__ float sigmoidf_(float x) { return 1.f / (1.f + expf(-x)); }

__device__ __forceinline__ unsigned f2tf32(float f) {
    unsigned r;
    asm("cvt.rna.tf32.f32 %0, %1;" : "=r"(r) : "f"(f));
    return r;
}

__device__ __forceinline__ float4 ld4(const float* p) { return *(const float4*)p; }
__device__ __forceinline__ void add4(float4& a, float4 b) {
    a.x += b.x; a.y += b.y; a.z += b.z; a.w += b.w;
}

// ---------------- generic 48xN small GEMM tile (M=48 full, tile N=64, BK=16) ----
struct __align__(16) SmemGemm { float As[16][52]; float Ws[16][68]; };

__device__ __forceinline__ void gemm48_tile(
    SmemGemm& sm,
    const float* __restrict__ A, int lda,
    const float* __restrict__ W, int ldw,
    float* __restrict__ C, int ldc,
    const float* __restrict__ bias,
    int N, int n0, int k0, int kc)
{
    int tid = threadIdx.x;
    int tx = tid & 15, ty = tid >> 4;
    float acc[3][4] = {{0.f,0.f,0.f,0.f},{0.f,0.f,0.f,0.f},{0.f,0.f,0.f,0.f}};

    for (int kk = 0; kk < kc; kk += 16) {
        if (tid < 192) {                         // A tile: 48 rows x 16 k
            int r = tid >> 2, kq = tid & 3;
            float4 v = *(const float4*)(A + r * lda + k0 + kk + kq * 4);
            sm.As[kq*4+0][r] = v.x; sm.As[kq*4+1][r] = v.y;
            sm.As[kq*4+2][r] = v.z; sm.As[kq*4+3][r] = v.w;
        }
        {                                        // W tile: 64 rows x 16 k
            int n = tid >> 2, kq = tid & 3;
            int gn = n0 + n;
            float4 v = make_float4(0.f, 0.f, 0.f, 0.f);
            if (gn < N) v = *(const float4*)(W + gn * ldw + k0 + kk + kq * 4);
            sm.Ws[kq*4+0][n] = v.x; sm.Ws[kq*4+1][n] = v.y;
            sm.Ws[kq*4+2][n] = v.z; sm.Ws[kq*4+3][n] = v.w;
        }
        __syncthreads();
        #pragma unroll
        for (int k = 0; k < 16; k++) {
            float a0 = sm.As[k][ty], a1 = sm.As[k][ty+16], a2 = sm.As[k][ty+32];
            float4 bv = *(const float4*)&sm.Ws[k][tx * 4];
            acc[0][0] += a0*bv.x; acc[0][1] += a0*bv.y; acc[0][2] += a0*bv.z; acc[0][3] += a0*bv.w;
            acc[1][0] += a1*bv.x; acc[1][1] += a1*bv.y; acc[1][2] += a1*bv.z; acc[1][3] += a1*bv.w;
            acc[2][0] += a2*bv.x; acc[2][1] += a2*bv.y; acc[2][2] += a2*bv.z; acc[2][3] += a2*bv.w;
        }
        __syncthreads();
    }
    #pragma unroll
    for (int i = 0; i < 3; i++) {
        int r = ty + i * 16;
        #pragma unroll
        for (int j = 0; j < 4; j++) {
            int n = n0 + tx * 4 + j;
            if (n < N) {
                float v = acc[i][j];
                if (bias) v += bias[n];
                C[r * ldc + n] = v;
            }
        }
    }
}

// ---------------- kernels ------------------------------------------------------

// emb_0 = start broadcast; stops[:,0] = 0
__global__ void seed_kernel(const float* __restrict__ start, float* __restrict__ out)
{
    int idx = blockIdx.x * 256 + threadIdx.x;
    if (idx < Bz * Ez) g_emb[idx] = start[idx & (Ez - 1)];
    if (idx < Bz) out[BTV + idx * Tz] = 0.f;
}

// h0 = latent @ W_lh^T + b_lh
__global__ void init_h_kernel(const float* __restrict__ latent,
                              const float* __restrict__ W_lh, const float* __restrict__ b_lh)
{
    __shared__ SmemGemm sm;
    gemm48_tile(sm, latent, Hz, W_lh, Hz, g_h[0], Hz, b_lh, Hz, blockIdx.x * 64, 0, Hz);
}

// peep = latent @ Wp^T + bp   (separate launch: also shifts ncu capture slot onto gates_kernel)
__global__ void init_peep_kernel(const float* __restrict__ latent,
                                 const float* __restrict__ Wp, const float* __restrict__ bp)
{
    __shared__ SmemGemm sm;
    gemm48_tile(sm, latent, Hz, Wp, Hz, g_peep, G3, bp, G3, blockIdx.x * 64, 0, Hz);
}

// split-K gate partials: p<4 -> ig (K=512 in 4 chunks), p>=4 -> hg (K=1024 in 8 chunks)
__global__ void gates_kernel(int s, const float* __restrict__ Wi, const float* __restrict__ Wh)
{
    __shared__ SmemGemm sm;
    int p = blockIdx.y;
    int n0 = blockIdx.x * 64;
    if (p < 4)
        gemm48_tile(sm, g_emb + s * Bz * Ez, Ez, Wi, Ez,
                    g_gpart[p], G3, nullptr, G3, n0, p * 128, 128);
    else
        gemm48_tile(sm, g_h[s & 1], Hz, Wh, Hz,
                    g_gpart[p], G3, nullptr, G3, n0, (p - 4) * 128, 128);
}

// gate elementwise: reduce partials (float4 over 4 j), compute hy -> h_new
// grid 96 x 128 = 12288 threads, each handles (b, j..j+3)
__global__ void __launch_bounds__(128) hy_kernel(int s, const float* __restrict__ bi,
                                                 const float* __restrict__ bh)
{
    int t = blockIdx.x * 128 + threadIdx.x;      // 0..12287
    int b  = t >> 8;                             // 0..47
    int jq = (t & 255) << 2;                     // 0..1020, step 4
    int base = b * G3;

    float4 ir = ld4(bi + jq);
    float4 ii = ld4(bi + Hz + jq);
    float4 in_ = ld4(bi + 2*Hz + jq);
    #pragma unroll
    for (int p = 0; p < 4; p++) {
        add4(ir,  ld4(&g_gpart[p][base + jq]));
        add4(ii,  ld4(&g_gpart[p][base + Hz + jq]));
        add4(in_, ld4(&g_gpart[p][base + 2*Hz + jq]));
    }
    float4 hr = ld4(bh + jq);
    float4 hi = ld4(bh + Hz + jq);
    float4 hn = ld4(bh + 2*Hz + jq);
    #pragma unroll
    for (int p = 4; p < 12; p++) {
        add4(hr, ld4(&g_gpart[p][base + jq]));
        add4(hi, ld4(&g_gpart[p][base + Hz + jq]));
        add4(hn, ld4(&g_gpart[p][base + 2*Hz + jq]));
    }
    float4 pr = ld4(&g_peep[base + jq]);
    float4 pi = ld4(&g_peep[base + Hz + jq]);
    float4 pn = ld4(&g_peep[base + 2*Hz + jq]);
    float4 hp = ld4(&g_h[s & 1][b * Hz + jq]);

    float4 res;
    {
        float r  = sigmoidf_(ir.x + hr.x + pr.x);
        float zi = sigmoidf_(ii.x + hi.x + pi.x);
        float n  = tanhf(in_.x + r * hn.x + pn.x);
        res.x = n + zi * (hp.x - n);
    }
    {
        float r  = sigmoidf_(ir.y + hr.y + pr.y);
        float zi = sigmoidf_(ii.y + hi.y + pi.y);
        float n  = tanhf(in_.y + r * hn.y + pn.y);
        res.y = n + zi * (hp.y - n);
    }
    {
        float r  = sigmoidf_(ir.z + hr.z + pr.z);
        float zi = sigmoidf_(ii.z + hi.z + pi.z);
        float n  = tanhf(in_.z + r * hn.z + pn.z);
        res.z = n + zi * (hp.z - n);
    }
    {
        float r  = sigmoidf_(ir.w + hr.w + pr.w);
        float zi = sigmoidf_(ii.w + hi.w + pi.w);
        float n  = tanhf(in_.w + r * hn.w + pn.w);
        res.w = n + zi * (hp.w - n);
    }
    *(float4*)&g_h[(s + 1) & 1][b * Hz + jq] = res;
}

// o = hy @ Wo^T (split-K 8 x 128) -> partials
__global__ void outp_kernel(int s, const float* __restrict__ Wo)
{
    __shared__ SmemGemm sm;
    int kc = blockIdx.y;                          // 0..7
    gemm48_tile(sm, g_h[(s + 1) & 1], Hz, Wo, Hz,
                g_opart + kc * Bz * OPLD, OPLD, nullptr, EP1,
                blockIdx.x * 64, kc * 128, 128);
}

// reduce o partials + bo; tanh -> emb_{s+1} (float4), sigmoid -> stop_{s+1}
// grid 25 x 256 = 6400 threads (6144 emb quads + 48 stop lanes)
__global__ void __launch_bounds__(256) reduce_kernel(int s, const float* __restrict__ bo,
                                                     float* __restrict__ out)
{
    int t = blockIdx.x * 256 + threadIdx.x;
    int ts = s + 1;
    if (t < 6144) {
        int b  = t >> 7;                          // 0..47
        int jq = (t & 127) << 2;                  // 0..508, step 4
        float4 v = ld4(bo + jq);
        #pragma unroll
        for (int k = 0; k < 8; k++)
            add4(v, ld4(g_opart + k * Bz * OPLD + b * OPLD + jq));
        float4 e = make_float4(tanhf(v.x), tanhf(v.y), tanhf(v.z), tanhf(v.w));
        *(float4*)&g_emb[(ts * Bz + b) * Ez + jq] = e;
    } else if (t < 6144 + Bz) {
        int b = t - 6144;
        float v = bo[Ez];
        #pragma unroll
        for (int k = 0; k < 8; k++)
            v += g_opart[k * Bz * OPLD + b * OPLD + Ez];
        out[BTV + b * Tz + ts] = sigmoidf_(v);
    }
}

// ---------------- unembed: tf32 tensor-core GEMM -------------------------------
// logits: (T*B=3072, E=512) @ Wu^T (V=32000) + bu -> out in (B,T,V) layout.
// Block tile 128x128, 8 warps (2x4), warp tile 64x32, mma.m16n8k8 tf32.
// Smem k-major tf32, pad 136 -> conflict-free fragment loads. Double-buffered.
__global__ void __launch_bounds__(256) unembed_kernel(
    const float* __restrict__ Wu, const float* __restrict__ bu, float* __restrict__ out)
{
    __shared__ unsigned As[2][16][136];
    __shared__ unsigned Bs[2][16][136];

    int tid  = threadIdx.x;
    int warp = tid >> 5, lane = tid & 31;
    int wm = warp >> 2, wn = warp & 3;            // 2 x 4 warp grid
    int m_warp = wm * 64, n_warp = wn * 32;
    int gID = lane >> 2, tig = lane & 3;

    const float* A  = g_emb + (size_t)blockIdx.y * 128 * Ez;
    const float* Bp = Wu    + (size_t)blockIdx.x * 128 * Ez;

    // loader coords: rows r0 and r0+64, 4 consecutive k at kq*4
    int r0 = tid >> 2, kq = tid & 3;

    float acc[4][4][4];
    #pragma unroll
    for (int mt = 0; mt < 4; mt++)
        #pragma unroll
        for (int nt = 0; nt < 4; nt++)
            #pragma unroll
            for (int c = 0; c < 4; c++) acc[mt][nt][c] = 0.f;

    // ---- preload stage 0 ----
    {
        #pragma unroll
        for (int u = 0; u < 2; u++) {
            int r = r0 + u * 64;
            float4 va = *(const float4*)(A  + r * Ez + kq * 4);
            float4 vb = *(const float4*)(Bp + r * Ez + kq * 4);
            As[0][kq*4+0][r] = f2tf32(va.x); As[0][kq*4+1][r] = f2tf32(va.y);
            As[0][kq*4+2][r] = f2tf32(va.z); As[0][kq*4+3][r] = f2tf32(va.w);
            Bs[0][kq*4+0][r] = f2tf32(vb.x); Bs[0][kq*4+1][r] = f2tf32(vb.y);
            Bs[0][kq*4+2][r] = f2tf32(vb.z); Bs[0][kq*4+3][r] = f2tf32(vb.w);
        }
    }
    __syncthreads();

    const int NT = Ez / 16;                       // 32 stages
    for (int it = 0; it < NT; it++) {
        int cur = it & 1;
        float4 va[2], vb[2];
        bool more = (it + 1 < NT);
        if (more) {
            int kt = (it + 1) * 16;
            #pragma unroll
            for (int u = 0; u < 2; u++) {
                int r = r0 + u * 64;
                va[u] = *(const float4*)(A  + r * Ez + kt + kq * 4);
                vb[u] = *(const float4*)(Bp + r * Ez + kt + kq * 4);
            }
        }

        #pragma unroll
        for (int ks = 0; ks < 2; ks++) {
            int k0 = ks * 8;
            unsigned a[4][4];
            #pragma unroll
            for (int mt = 0; mt < 4; mt++) {
                int m0 = m_warp + mt * 16;
                a[mt][0] = As[cur][k0 + tig    ][m0 + gID    ];
                a[mt][1] = As[cur][k0 + tig    ][m0 + gID + 8];
                a[mt][2] = As[cur][k0 + tig + 4][m0 + gID    ];
                a[mt][3] = As[cur][k0 + tig + 4][m0 + gID + 8];
            }
            unsigned b[4][2];
            #pragma unroll
            for (int nt = 0; nt < 4; nt++) {
                int n0 = n_warp + nt * 8;
                b[nt][0] = Bs[cur][k0 + tig    ][n0 + gID];
                b[nt][1] = Bs[cur][k0 + tig + 4][n0 + gID];
            }
            #pragma unroll
            for (int mt = 0; mt < 4; mt++)
                #pragma unroll
                for (int nt = 0; nt < 4; nt++) {
                    asm volatile(
                        "mma.sync.aligned.m16n8k8.row.col.f32.tf32.tf32.f32 "
                        "{%0,%1,%2,%3}, {%4,%5,%6,%7}, {%8,%9}, {%0,%1,%2,%3};"
                        : "+f"(acc[mt][nt][0]), "+f"(acc[mt][nt][1]),
                          "+f"(acc[mt][nt][2]), "+f"(acc[mt][nt][3])
                        : "r"(a[mt][0]), "r"(a[mt][1]), "r"(a[mt][2]), "r"(a[mt][3]),
                          "r"(b[nt][0]), "r"(b[nt][1]));
                }
        }

        if (more) {
            int nxt = cur ^ 1;
            #pragma unroll
            for (int u = 0; u < 2; u++) {
                int r = r0 + u * 64;
                As[nxt][kq*4+0][r] = f2tf32(va[u].x); As[nxt][kq*4+1][r] = f2tf32(va[u].y);
                As[nxt][kq*4+2][r] = f2tf32(va[u].z); As[nxt][kq*4+3][r] = f2tf32(va[u].w);
                Bs[nxt][kq*4+0][r] = f2tf32(vb[u].x); Bs[nxt][kq*4+1][r] = f2tf32(vb[u].y);
                Bs[nxt][kq*4+2][r] = f2tf32(vb[u].z); Bs[nxt][kq*4+3][r] = f2tf32(vb[u].w);
            }
            __syncthreads();
        }
    }

    // ---- epilogue: bias + direct stores ----
    #pragma unroll
    for (int nt = 0; nt < 4; nt++) {
        int col = blockIdx.x * 128 + n_warp + nt * 8 + 2 * tig;
        float bv0 = bu[col], bv1 = bu[col + 1];
        #pragma unroll
        for (int mt = 0; mt < 4; mt++) {
            int m_lo = blockIdx.y * 128 + m_warp + mt * 16 + gID;
            #pragma unroll
            for (int half = 0; half < 2; half++) {
                int m = m_lo + half * 8;
                int t = m / Bz, b = m % Bz;
                float* dst = out + (size_t)b * (Tz * Vz) + (size_t)t * Vz + col;
                float2 v = make_float2(acc[mt][nt][half*2+0] + bv0,
                                       acc[mt][nt][half*2+1] + bv1);
                *(float2*)dst = v;
            }
        }
    }
}

// ---------------- host ---------------------------------------------------------
extern "C" void kernel_launch(void* const* d_in, const int* in_sizes, int n_in,
                              void* d_out, int out_size)
{
    const float* latent = (const float*)d_in[1];
    const float* Wi     = (const float*)d_in[2];
    const float* bi     = (const float*)d_in[3];
    const float* Wh     = (const float*)d_in[4];
    const float* bh     = (const float*)d_in[5];
    const float* Wp     = (const float*)d_in[6];
    const float* bp     = (const float*)d_in[7];
    const float* W_lh   = (const float*)d_in[8];
    const float* b_lh   = (const float*)d_in[9];
    const float* Wo     = (const float*)d_in[10];
    const float* bo     = (const float*)d_in[11];
    const float* Wu     = (const float*)d_in[12];
    const float* bu     = (const float*)d_in[13];
    const float* start  = (const float*)d_in[14];
    float* out = (float*)d_out;

    seed_kernel<<<96, 256>>>(start, out);
    init_h_kernel<<<16, 256>>>(latent, W_lh, b_lh);
    init_peep_kernel<<<48, 256>>>(latent, Wp, bp);

    for (int s = 0; s < Tz - 1; s++) {
        gates_kernel<<<dim3(48, NPART), 256>>>(s, Wi, Wh);
        hy_kernel<<<96, 128>>>(s, bi, bh);
        outp_kernel<<<dim3(9, 8), 256>>>(s, Wo);
        reduce_kernel<<<25, 256>>>(s, bo, out);
    }

    unembed_kernel<<<dim3(Vz / 128, (Tz * Bz) / 128), 256>>>(Wu, bu, out);
}

// round 7
// speedup vs baseline: 1.1909x; 1.1909x over previous
#include <cuda_runtime.h>
#include <cuda_bf16.h>
#include <math.h>

#define Bz  48
#define Ez  512
#define Hz  1024
#define Vz  32000
#define Tz  64
#define G3  3072            // 3*H
#define OPLD 544            // padded cols for o partials (68 n-tiles * 8)
#define NTO 68              // n-tiles for output projection
#define BTV (Bz*Tz*Vz)

// ---------------- scratch (static device memory) --------------------------------
__device__ float g_emb[Tz * Bz * Ez];        // emb_t fp32 (unembed input)
__device__ float g_h[2][Bz * Hz];            // hidden fp32 ping-pong
__device__ float g_peep[Bz * G3];
__device__ float g_gp3[3][Bz * G3];          // gate partials (3 K-parts)
__device__ float g_opart[8][Bz * OPLD];      // outp partials (8 K-parts)

// packed gate/out weights: bf16 hi/lo in B-fragment order, uint2 {b0,b1} per lane
__device__ uint2 g_Wg_hi[384 * 96 * 32];     // [Wi|Wh] 3072x1536
__device__ uint2 g_Wg_lo[384 * 96 * 32];
__device__ uint2 g_Wo_hi[NTO * 64 * 32];     // Wo padded 544x1024
__device__ uint2 g_Wo_lo[NTO * 64 * 32];

// activation A-fragments: uint4 {a0,a1,a2,a3} per (kchunk, mtile, lane)
__device__ uint4 g_eF_hi[32 * 3 * 32];       // emb (K=512 -> 32 chunks)
__device__ uint4 g_eF_lo[32 * 3 * 32];
__device__ uint4 g_hF_hi[64 * 3 * 32];       // h (K=1024 -> 64 chunks)
__device__ uint4 g_hF_lo[64 * 3 * 32];

__device__ __forceinline__ float sigmoidf_(float x) { return 1.f / (1.f + expf(-x)); }

__device__ __forceinline__ unsigned f2tf32(float f) {
    unsigned r; asm("cvt.rna.tf32.f32 %0, %1;" : "=r"(r) : "f"(f)); return r;
}
__device__ __forceinline__ float4 ld4(const float* p) { return *(const float4*)p; }
__device__ __forceinline__ void add4(float4& a, float4 b) {
    a.x += b.x; a.y += b.y; a.z += b.z; a.w += b.w;
}

// pack two floats to bf16x2 (low half = first element), return residuals
__device__ __forceinline__ unsigned pk_hi(float x, float y, float& rx, float& ry) {
    __nv_bfloat162 h = __floats2bfloat162_rn(x, y);
    rx = x - __bfloat162float(h.x);
    ry = y - __bfloat162float(h.y);
    return *reinterpret_cast<unsigned*>(&h);
}
__device__ __forceinline__ unsigned pk(float x, float y) {
    __nv_bfloat162 h = __floats2bfloat162_rn(x, y);
    return *reinterpret_cast<unsigned*>(&h);
}

// uint index (into uint-view of frag array) for A element-pair (row r, k-pair kp)
__device__ __forceinline__ int afrag_u(int r, int kp) {
    int kc = kp >> 3, tp = kp & 7;
    int m = r >> 4, rr = r & 15;
    int lane = ((rr & 7) << 2) | (tp & 3);
    int slot = ((tp >> 2) << 1) | (rr >> 3);
    return ((((kc * 3 + m) << 5) | lane) << 2) | slot;
}

// m16n8k16 bf16 mma, fp32 accumulate
__device__ __forceinline__ void mma_bf16(float* c, uint4 a, unsigned b0, unsigned b1) {
    asm volatile(
        "mma.sync.aligned.m16n8k16.row.col.f32.bf16.bf16.f32 "
        "{%0,%1,%2,%3}, {%4,%5,%6,%7}, {%8,%9}, {%0,%1,%2,%3};"
        : "+f"(c[0]), "+f"(c[1]), "+f"(c[2]), "+f"(c[3])
        : "r"(a.x), "r"(a.y), "r"(a.z), "r"(a.w), "r"(b0), "r"(b1));
}

// ---------------- weight packing (once per launch) -------------------------------
__global__ void pack_wg(const float* __restrict__ Wi, const float* __restrict__ Wh)
{
    int idx = blockIdx.x * 256 + threadIdx.x;
    if (idx >= 384 * 96 * 32) return;
    int lane = idx & 31;
    int t2 = idx >> 5;
    int kc = t2 % 96, nt = t2 / 96;
    int n = nt * 8 + (lane >> 2);
    int k0 = kc * 16 + 2 * (lane & 3);
    const float* src; int kk;
    if (kc < 32) { src = Wi + n * Ez; kk = k0; }
    else         { src = Wh + n * Hz; kk = k0 - Ez; }
    float w00 = src[kk],     w01 = src[kk + 1];
    float w10 = src[kk + 8], w11 = src[kk + 9];
    float r00, r01, r10, r11;
    unsigned h0 = pk_hi(w00, w01, r00, r01);
    unsigned h1 = pk_hi(w10, w11, r10, r11);
    g_Wg_hi[idx] = make_uint2(h0, h1);
    g_Wg_lo[idx] = make_uint2(pk(r00, r01), pk(r10, r11));
}

__global__ void pack_wo(const float* __restrict__ Wo)
{
    int idx = blockIdx.x * 256 + threadIdx.x;
    if (idx >= NTO * 64 * 32) return;
    int lane = idx & 31;
    int kc = (idx >> 5) & 63, nt = idx >> 11;
    int n = nt * 8 + (lane >> 2);
    int k0 = kc * 16 + 2 * (lane & 3);
    float w00 = 0.f, w01 = 0.f, w10 = 0.f, w11 = 0.f;
    if (n < Ez + 1) {
        const float* src = Wo + n * Hz;
        w00 = src[k0]; w01 = src[k0 + 1]; w10 = src[k0 + 8]; w11 = src[k0 + 9];
    }
    float r00, r01, r10, r11;
    unsigned h0 = pk_hi(w00, w01, r00, r01);
    unsigned h1 = pk_hi(w10, w11, r10, r11);
    g_Wo_hi[idx] = make_uint2(h0, h1);
    g_Wo_lo[idx] = make_uint2(pk(r00, r01), pk(r10, r11));
}

// ---------------- init ------------------------------------------------------------

// emb_0 fp32 + emb_0 fragments + stops[:,0] = 0
__global__ void seed_kernel(const float* __restrict__ start, float* __restrict__ out)
{
    int idx = blockIdx.x * 256 + threadIdx.x;          // grid 96*256 = 24576
    if (idx < Bz * Ez) g_emb[idx] = start[idx & (Ez - 1)];
    if (idx < Bz * 256) {                              // 12288 pair positions
        int r = idx >> 8, kp = idx & 255;
        float x = start[2 * kp], y = start[2 * kp + 1];
        float rx, ry;
        ((unsigned*)g_eF_hi)[afrag_u(r, kp)] = pk_hi(x, y, rx, ry);
        ((unsigned*)g_eF_lo)[afrag_u(r, kp)] = pk(rx, ry);
    }
    if (idx < Bz) out[BTV + idx * Tz] = 0.f;
}

// fp32 48xN GEMM for init (h0, peep)
struct __align__(16) SmemGemm { float As[16][52]; float Ws[16][68]; };

__device__ __forceinline__ void gemm48_tile(
    SmemGemm& sm, const float* __restrict__ A, int lda,
    const float* __restrict__ W, int ldw,
    float* __restrict__ C, int ldc, const float* __restrict__ bias,
    int N, int n0, int k0, int kc)
{
    int tid = threadIdx.x;
    int tx = tid & 15, ty = tid >> 4;
    float acc[3][4] = {{0,0,0,0},{0,0,0,0},{0,0,0,0}};
    for (int kk = 0; kk < kc; kk += 16) {
        if (tid < 192) {
            int r = tid >> 2, kq = tid & 3;
            float4 v = *(const float4*)(A + r * lda + k0 + kk + kq * 4);
            sm.As[kq*4+0][r] = v.x; sm.As[kq*4+1][r] = v.y;
            sm.As[kq*4+2][r] = v.z; sm.As[kq*4+3][r] = v.w;
        }
        {
            int n = tid >> 2, kq = tid & 3;
            int gn = n0 + n;
            float4 v = make_float4(0.f,0.f,0.f,0.f);
            if (gn < N) v = *(const float4*)(W + gn * ldw + k0 + kk + kq * 4);
            sm.Ws[kq*4+0][n] = v.x; sm.Ws[kq*4+1][n] = v.y;
            sm.Ws[kq*4+2][n] = v.z; sm.Ws[kq*4+3][n] = v.w;
        }
        __syncthreads();
        #pragma unroll
        for (int k = 0; k < 16; k++) {
            float a0 = sm.As[k][ty], a1 = sm.As[k][ty+16], a2 = sm.As[k][ty+32];
            float4 bv = *(const float4*)&sm.Ws[k][tx * 4];
            acc[0][0]+=a0*bv.x; acc[0][1]+=a0*bv.y; acc[0][2]+=a0*bv.z; acc[0][3]+=a0*bv.w;
            acc[1][0]+=a1*bv.x; acc[1][1]+=a1*bv.y; acc[1][2]+=a1*bv.z; acc[1][3]+=a1*bv.w;
            acc[2][0]+=a2*bv.x; acc[2][1]+=a2*bv.y; acc[2][2]+=a2*bv.z; acc[2][3]+=a2*bv.w;
        }
        __syncthreads();
    }
    #pragma unroll
    for (int i = 0; i < 3; i++) {
        int r = ty + i * 16;
        #pragma unroll
        for (int j = 0; j < 4; j++) {
            int n = n0 + tx * 4 + j;
            if (n < N) { float v = acc[i][j]; if (bias) v += bias[n]; C[r*ldc + n] = v; }
        }
    }
}

__global__ void init_kernel(const float* __restrict__ latent,
                            const float* __restrict__ W_lh, const float* __restrict__ b_lh,
                            const float* __restrict__ Wp,   const float* __restrict__ bp)
{
    __shared__ SmemGemm sm;
    if (blockIdx.x < 16)
        gemm48_tile(sm, latent, Hz, W_lh, Hz, g_h[0], Hz, b_lh, Hz, blockIdx.x * 64, 0, Hz);
    else
        gemm48_tile(sm, latent, Hz, Wp, Hz, g_peep, G3, bp, G3, (blockIdx.x - 16) * 64, 0, Hz);
}

// h0 -> A fragments
__global__ void pack_h0()
{
    int idx = blockIdx.x * 256 + threadIdx.x;          // grid 96*256 = 24576
    if (idx >= Bz * 512) return;
    int r = idx >> 9, kp = idx & 511;
    float x = g_h[0][r * Hz + 2 * kp], y = g_h[0][r * Hz + 2 * kp + 1];
    float rx, ry;
    ((unsigned*)g_hF_hi)[afrag_u(r, kp)] = pk_hi(x, y, rx, ry);
    ((unsigned*)g_hF_lo)[afrag_u(r, kp)] = pk(rx, ry);
}

// ---------------- recurrence: tensorized gate GEMM -------------------------------
// C[48,3072] partial = A(emb|h slice) @ Wg_slice^T, split-bf16 3-pass.
// grid (48, 3): nblk = 64-col slice, kpart = K third (emb | h[0:512] | h[512:1024]).
__global__ void __launch_bounds__(128) gates_mma()
{
    int w = threadIdx.x >> 5, lane = threadIdx.x & 31;
    int nblk = blockIdx.x, kpart = blockIdx.y;

    const uint4 *Ah, *Al; int cbase;
    if (kpart == 0) { Ah = g_eF_hi; Al = g_eF_lo; cbase = 0; }
    else            { Ah = g_hF_hi; Al = g_hF_lo; cbase = (kpart - 1) * 32; }

    int nt0 = nblk * 8 + w * 2;
    const uint2* B0h = g_Wg_hi + (nt0 * 96 + kpart * 32) * 32;
    const uint2* B0l = g_Wg_lo + (nt0 * 96 + kpart * 32) * 32;
    const uint2* B1h = g_Wg_hi + ((nt0 + 1) * 96 + kpart * 32) * 32;
    const uint2* B1l = g_Wg_lo + ((nt0 + 1) * 96 + kpart * 32) * 32;

    float acc[2][3][4];
    #pragma unroll
    for (int j = 0; j < 2; j++)
        #pragma unroll
        for (int m = 0; m < 3; m++)
            #pragma unroll
            for (int c = 0; c < 4; c++) acc[j][m][c] = 0.f;

    #pragma unroll 2
    for (int c = 0; c < 32; c++) {
        const uint4* ab = Ah + ((cbase + c) * 3) * 32 + lane;
        const uint4* al_ = Al + ((cbase + c) * 3) * 32 + lane;
        uint4 ah[3] = { ab[0], ab[32], ab[64] };
        uint4 alr[3] = { al_[0], al_[32], al_[64] };
        uint2 bh0 = B0h[c * 32 + lane], bl0 = B0l[c * 32 + lane];
        uint2 bh1 = B1h[c * 32 + lane], bl1 = B1l[c * 32 + lane];
        #pragma unroll
        for (int m = 0; m < 3; m++) {
            mma_bf16(acc[0][m], ah[m],  bh0.x, bh0.y);
            mma_bf16(acc[0][m], ah[m],  bl0.x, bl0.y);
            mma_bf16(acc[0][m], alr[m], bh0.x, bh0.y);
            mma_bf16(acc[1][m], ah[m],  bh1.x, bh1.y);
            mma_bf16(acc[1][m], ah[m],  bl1.x, bl1.y);
            mma_bf16(acc[1][m], alr[m], bh1.x, bh1.y);
        }
    }

    int g = lane >> 2, tig = lane & 3;
    float* C = g_gp3[kpart];
    #pragma unroll
    for (int j = 0; j < 2; j++) {
        int col = (nt0 + j) * 8 + 2 * tig;
        #pragma unroll
        for (int m = 0; m < 3; m++) {
            int r0 = m * 16 + g;
            *(float2*)&C[r0 * G3 + col]       = make_float2(acc[j][m][0], acc[j][m][1]);
            *(float2*)&C[(r0 + 8) * G3 + col] = make_float2(acc[j][m][2], acc[j][m][3]);
        }
    }
}

// gate elementwise: sum 3 partials + biases + peep -> hy; write fp32 + fragments
__global__ void __launch_bounds__(256) hy_kernel(int s, const float* __restrict__ bi,
                                                 const float* __restrict__ bh)
{
    int t = blockIdx.x * 256 + threadIdx.x;            // 48 blocks -> 12288
    int b = t >> 8, jq = (t & 255) << 2;
    int base = b * G3;

    float4 gr = ld4(bi + jq);           add4(gr, ld4(bh + jq));
    float4 gi = ld4(bi + Hz + jq);      add4(gi, ld4(bh + Hz + jq));
    float4 gn = ld4(bi + 2*Hz + jq);    add4(gn, ld4(bh + 2*Hz + jq));
    #pragma unroll
    for (int p = 0; p < 3; p++) {
        add4(gr, ld4(&g_gp3[p][base + jq]));
        add4(gi, ld4(&g_gp3[p][base + Hz + jq]));
        add4(gn, ld4(&g_gp3[p][base + 2*Hz + jq]));
    }
    add4(gr, ld4(&g_peep[base + jq]));
    add4(gi, ld4(&g_peep[base + Hz + jq]));
    add4(gn, ld4(&g_peep[base + 2*Hz + jq]));
    float4 hp = ld4(&g_h[s & 1][b * Hz + jq]);

    float4 res;
    {
        float r = sigmoidf_(gr.x), zi = sigmoidf_(gi.x);
        float n = tanhf(gn.x - gr.x * 0.f + (r - 1.f) * 0.f + (r * (gn.x - gn.x)) + gn.x * 0.f + (gn.x - gn.x));
        // (the line above is a placeholder guard; real computation below)
        n = tanhf(0.f); (void)n;
        res.x = 0.f; (void)zi;
    }
    // --- real gate math (newgate uses resetgate * h_n, so recompute properly) ---
    // gn currently holds i_n + h_n_sum + p_n which is WRONG for the reset gating;
    // we must keep h_n separate. Redo with separate accumulation:
    {
        // reload: i_n + p_n + bi_n  vs  h_n + bh_n must be gated separately.
        // h-side n partial = gp3[1] + gp3[2] (from Wh) at 2Hz; i-side = gp3[0] + bi.
        float4 in_ = ld4(bi + 2*Hz + jq);
        add4(in_, ld4(&g_gp3[0][base + 2*Hz + jq]));
        add4(in_, ld4(&g_peep[base + 2*Hz + jq]));
        float4 hn = ld4(bh + 2*Hz + jq);
        add4(hn, ld4(&g_gp3[1][base + 2*Hz + jq]));
        add4(hn, ld4(&g_gp3[2][base + 2*Hz + jq]));

        float r0 = sigmoidf_(gr.x), r1 = sigmoidf_(gr.y), r2 = sigmoidf_(gr.z), r3 = sigmoidf_(gr.w);
        float z0 = sigmoidf_(gi.x), z1 = sigmoidf_(gi.y), z2 = sigmoidf_(gi.z), z3 = sigmoidf_(gi.w);
        float n0 = tanhf(in_.x + r0 * hn.x);
        float n1 = tanhf(in_.y + r1 * hn.y);
        float n2 = tanhf(in_.z + r2 * hn.z);
        float n3 = tanhf(in_.w + r3 * hn.w);
        res.x = n0 + z0 * (hp.x - n0);
        res.y = n1 + z1 * (hp.y - n1);
        res.z = n2 + z2 * (hp.z - n2);
        res.w = n3 + z3 * (hp.w - n3);
    }

    *(float4*)&g_h[(s + 1) & 1][b * Hz + jq] = res;

    int kp = jq >> 1;
    float rx, ry;
    unsigned u0 = pk_hi(res.x, res.y, rx, ry);
    ((unsigned*)g_hF_hi)[afrag_u(b, kp)] = u0;
    ((unsigned*)g_hF_lo)[afrag_u(b, kp)] = pk(rx, ry);
    unsigned u1 = pk_hi(res.z, res.w, rx, ry);
    ((unsigned*)g_hF_hi)[afrag_u(b, kp + 1)] = u1;
    ((unsigned*)g_hF_lo)[afrag_u(b, kp + 1)] = pk(rx, ry);
}

// o = hy @ Wo^T, split-bf16 3-pass, split-K 8. grid (17, 8), 128 thr.
__global__ void __launch_bounds__(128) outp_mma()
{
    int w = threadIdx.x >> 5, lane = threadIdx.x & 31;
    int nt = blockIdx.x * 4 + w;                        // 0..67
    int kbase = blockIdx.y * 8;                         // h chunk base

    const uint2* Bh = g_Wo_hi + (nt * 64 + kbase) * 32;
    const uint2* Bl = g_Wo_lo + (nt * 64 + kbase) * 32;

    float acc[3][4];
    #pragma unroll
    for (int m = 0; m < 3; m++)
        #pragma unroll
        for (int c = 0; c < 4; c++) acc[m][c] = 0.f;

    #pragma unroll
    for (int c = 0; c < 8; c++) {
        const uint4* ab = g_hF_hi + ((kbase + c) * 3) * 32 + lane;
        const uint4* al_ = g_hF_lo + ((kbase + c) * 3) * 32 + lane;
        uint4 ah[3] = { ab[0], ab[32], ab[64] };
        uint4 alr[3] = { al_[0], al_[32], al_[64] };
        uint2 bh = Bh[c * 32 + lane], bl = Bl[c * 32 + lane];
        #pragma unroll
        for (int m = 0; m < 3; m++) {
            mma_bf16(acc[m], ah[m],  bh.x, bh.y);
            mma_bf16(acc[m], ah[m],  bl.x, bl.y);
            mma_bf16(acc[m], alr[m], bh.x, bh.y);
        }
    }

    int g = lane >> 2, tig = lane & 3;
    int col = nt * 8 + 2 * tig;
    float* C = g_opart[blockIdx.y];
    #pragma unroll
    for (int m = 0; m < 3; m++) {
        int r0 = m * 16 + g;
        *(float2*)&C[r0 * OPLD + col]       = make_float2(acc[m][0], acc[m][1]);
        *(float2*)&C[(r0 + 8) * OPLD + col] = make_float2(acc[m][2], acc[m][3]);
    }
}

// reduce o partials + bo; tanh -> emb fp32 + fragments; sigmoid -> stop
__global__ void __launch_bounds__(256) reduce_kernel(int s, const float* __restrict__ bo,
                                                     float* __restrict__ out)
{
    int t = blockIdx.x * 256 + threadIdx.x;
    int ts = s + 1;
    if (t < 6144) {
        int b = t >> 7, jq = (t & 127) << 2;
        float4 v = ld4(bo + jq);
        #pragma unroll
        for (int k = 0; k < 8; k++)
            add4(v, ld4(&g_opart[k][b * OPLD + jq]));
        float4 e = make_float4(tanhf(v.x), tanhf(v.y), tanhf(v.z), tanhf(v.w));
        *(float4*)&g_emb[(ts * Bz + b) * Ez + jq] = e;
        int kp = jq >> 1;
        float rx, ry;
        unsigned u0 = pk_hi(e.x, e.y, rx, ry);
        ((unsigned*)g_eF_hi)[afrag_u(b, kp)] = u0;
        ((unsigned*)g_eF_lo)[afrag_u(b, kp)] = pk(rx, ry);
        unsigned u1 = pk_hi(e.z, e.w, rx, ry);
        ((unsigned*)g_eF_hi)[afrag_u(b, kp + 1)] = u1;
        ((unsigned*)g_eF_lo)[afrag_u(b, kp + 1)] = pk(rx, ry);
    } else if (t < 6144 + Bz) {
        int b = t - 6144;
        float v = bo[Ez];
        #pragma unroll
        for (int k = 0; k < 8; k++)
            v += g_opart[k][b * OPLD + Ez];
        out[BTV + b * Tz + ts] = sigmoidf_(v);
    }
}

// ---------------- unembed: tf32 tensor-core GEMM (unchanged from R5) -------------
__global__ void __launch_bounds__(256) unembed_kernel(
    const float* __restrict__ Wu, const float* __restrict__ bu, float* __restrict__ out)
{
    __shared__ unsigned As[2][16][136];
    __shared__ unsigned Bs[2][16][136];

    int tid  = threadIdx.x;
    int warp = tid >> 5, lane = tid & 31;
    int wm = warp >> 2, wn = warp & 3;
    int m_warp = wm * 64, n_warp = wn * 32;
    int gID = lane >> 2, tig = lane & 3;

    const float* A  = g_emb + (size_t)blockIdx.y * 128 * Ez;
    const float* Bp = Wu    + (size_t)blockIdx.x * 128 * Ez;
    int r0 = tid >> 2, kq = tid & 3;

    float acc[4][4][4];
    #pragma unroll
    for (int mt = 0; mt < 4; mt++)
        #pragma unroll
        for (int nt = 0; nt < 4; nt++)
            #pragma unroll
            for (int c = 0; c < 4; c++) acc[mt][nt][c] = 0.f;

    {
        #pragma unroll
        for (int u = 0; u < 2; u++) {
            int r = r0 + u * 64;
            float4 va = *(const float4*)(A  + r * Ez + kq * 4);
            float4 vb = *(const float4*)(Bp + r * Ez + kq * 4);
            As[0][kq*4+0][r]=f2tf32(va.x); As[0][kq*4+1][r]=f2tf32(va.y);
            As[0][kq*4+2][r]=f2tf32(va.z); As[0][kq*4+3][r]=f2tf32(va.w);
            Bs[0][kq*4+0][r]=f2tf32(vb.x); Bs[0][kq*4+1][r]=f2tf32(vb.y);
            Bs[0][kq*4+2][r]=f2tf32(vb.z); Bs[0][kq*4+3][r]=f2tf32(vb.w);
        }
    }
    __syncthreads();

    const int NT = Ez / 16;
    for (int it = 0; it < NT; it++) {
        int cur = it & 1;
        float4 va[2], vb[2];
        bool more = (it + 1 < NT);
        if (more) {
            int kt = (it + 1) * 16;
            #pragma unroll
            for (int u = 0; u < 2; u++) {
                int r = r0 + u * 64;
                va[u] = *(const float4*)(A  + r * Ez + kt + kq * 4);
                vb[u] = *(const float4*)(Bp + r * Ez + kt + kq * 4);
            }
        }
        #pragma unroll
        for (int ks = 0; ks < 2; ks++) {
            int k0 = ks * 8;
            unsigned a[4][4];
            #pragma unroll
            for (int mt = 0; mt < 4; mt++) {
                int m0 = m_warp + mt * 16;
                a[mt][0] = As[cur][k0 + tig    ][m0 + gID    ];
                a[mt][1] = As[cur][k0 + tig    ][m0 + gID + 8];
                a[mt][2] = As[cur][k0 + tig + 4][m0 + gID    ];
                a[mt][3] = As[cur][k0 + tig + 4][m0 + gID + 8];
            }
            unsigned b[4][2];
            #pragma unroll
            for (int nt = 0; nt < 4; nt++) {
                int n0 = n_warp + nt * 8;
                b[nt][0] = Bs[cur][k0 + tig    ][n0 + gID];
                b[nt][1] = Bs[cur][k0 + tig + 4][n0 + gID];
            }
            #pragma unroll
            for (int mt = 0; mt < 4; mt++)
                #pragma unroll
                for (int nt = 0; nt < 4; nt++) {
                    asm volatile(
                        "mma.sync.aligned.m16n8k8.row.col.f32.tf32.tf32.f32 "
                        "{%0,%1,%2,%3}, {%4,%5,%6,%7}, {%8,%9}, {%0,%1,%2,%3};"
                        : "+f"(acc[mt][nt][0]), "+f"(acc[mt][nt][1]),
                          "+f"(acc[mt][nt][2]), "+f"(acc[mt][nt][3])
                        : "r"(a[mt][0]), "r"(a[mt][1]), "r"(a[mt][2]), "r"(a[mt][3]),
                          "r"(b[nt][0]), "r"(b[nt][1]));
                }
        }
        if (more) {
            int nxt = cur ^ 1;
            #pragma unroll
            for (int u = 0; u < 2; u++) {
                int r = r0 + u * 64;
                As[nxt][kq*4+0][r]=f2tf32(va[u].x); As[nxt][kq*4+1][r]=f2tf32(va[u].y);
                As[nxt][kq*4+2][r]=f2tf32(va[u].z); As[nxt][kq*4+3][r]=f2tf32(va[u].w);
                Bs[nxt][kq*4+0][r]=f2tf32(vb[u].x); Bs[nxt][kq*4+1][r]=f2tf32(vb[u].y);
                Bs[nxt][kq*4+2][r]=f2tf32(vb[u].z); Bs[nxt][kq*4+3][r]=f2tf32(vb[u].w);
            }
            __syncthreads();
        }
    }

    #pragma unroll
    for (int nt = 0; nt < 4; nt++) {
        int col = blockIdx.x * 128 + n_warp + nt * 8 + 2 * tig;
        float bv0 = bu[col], bv1 = bu[col + 1];
        #pragma unroll
        for (int mt = 0; mt < 4; mt++) {
            int m_lo = blockIdx.y * 128 + m_warp + mt * 16 + gID;
            #pragma unroll
            for (int half = 0; half < 2; half++) {
                int m = m_lo + half * 8;
                int t = m / Bz, b = m % Bz;
                float* dst = out + (size_t)b * (Tz * Vz) + (size_t)t * Vz + col;
                *(float2*)dst = make_float2(acc[mt][nt][half*2+0] + bv0,
                                            acc[mt][nt][half*2+1] + bv1);
            }
        }
    }
}

// ---------------- host -----------------------------------------------------------
extern "C" void kernel_launch(void* const* d_in, const int* in_sizes, int n_in,
                              void* d_out, int out_size)
{
    const float* latent = (const float*)d_in[1];
    const float* Wi     = (const float*)d_in[2];
    const float* bi     = (const float*)d_in[3];
    const float* Wh     = (const float*)d_in[4];
    const float* bh     = (const float*)d_in[5];
    const float* Wp     = (const float*)d_in[6];
    const float* bp     = (const float*)d_in[7];
    const float* W_lh   = (const float*)d_in[8];
    const float* b_lh   = (const float*)d_in[9];
    const float* Wo     = (const float*)d_in[10];
    const float* bo     = (const float*)d_in[11];
    const float* Wu     = (const float*)d_in[12];
    const float* bu     = (const float*)d_in[13];
    const float* start  = (const float*)d_in[14];
    float* out = (float*)d_out;

    pack_wg<<<4608, 256>>>(Wi, Wh);
    pack_wo<<<544, 256>>>(Wo);
    seed_kernel<<<96, 256>>>(start, out);
    init_kernel<<<64, 256>>>(latent, W_lh, b_lh, Wp, bp);
    pack_h0<<<96, 256>>>();

    for (int s = 0; s < Tz - 1; s++) {
        gates_mma<<<dim3(48, 3), 128>>>();
        hy_kernel<<<48, 256>>>(s, bi, bh);
        outp_mma<<<dim3(17, 8), 128>>>();
        reduce_kernel<<<25, 256>>>(s, bo, out);
    }

    unembed_kernel<<<dim3(Vz / 128, (Tz * Bz) / 128), 256>>>(Wu, bu, out);
}

// round 8
// speedup vs baseline: 1.8103x; 1.5201x over previous
#include <cuda_runtime.h>
#include <cuda_bf16.h>
#include <math.h>

#define Bz  48
#define Ez  512
#define Hz  1024
#define Vz  32000
#define Tz  64
#define G3  3072
#define BTV (Bz*Tz*Vz)
#define NB  128            // persistent blocks

// ---------------- scratch (static device memory) --------------------------------
__device__ float g_emb[Tz * Bz * Ez];          // emb_t fp32 (unembed input)
__device__ float g_h[2][Bz * Hz];              // hidden fp32 ping-pong
__device__ float g_peep[Bz * G3];
__device__ float g_ipart[4][Bz * 4096];        // init split-K partials (h0 | peep)

// packed weights: bf16 hi/lo in B-fragment order, uint2 {b0,b1} per lane
__device__ uint2 g_Wg_hi[384 * 96 * 32];       // [Wi|Wh] 3072x1536
__device__ uint2 g_Wg_lo[384 * 96 * 32];
__device__ uint2 g_Wo_hi[65 * 64 * 32];        // Wo 513x1024 (padded to 520 rows)
__device__ uint2 g_Wo_lo[65 * 64 * 32];

// activation A-fragments (uint4 per (kchunk, mtile, lane))
__device__ uint4 g_eF_hi[32 * 3 * 32];         // emb (K=512)
__device__ uint4 g_eF_lo[32 * 3 * 32];
__device__ uint4 g_hF_hi[2][64 * 3 * 32];      // h (K=1024), ping-pong
__device__ uint4 g_hF_lo[2][64 * 3 * 32];

// grid barrier state (zero-init; count returns to 0 each use -> graph-replay safe)
__device__ unsigned g_bar_cnt;
__device__ unsigned g_bar_gen;

__device__ __forceinline__ float sigmoidf_(float x) { return 1.f / (1.f + expf(-x)); }

__device__ __forceinline__ unsigned f2tf32(float f) {
    unsigned r; asm("cvt.rna.tf32.f32 %0, %1;" : "=r"(r) : "f"(f)); return r;
}
__device__ __forceinline__ float4 ld4(const float* p) { return *(const float4*)p; }
__device__ __forceinline__ void add4(float4& a, float4 b) {
    a.x += b.x; a.y += b.y; a.z += b.z; a.w += b.w;
}
__device__ __forceinline__ unsigned pk_hi(float x, float y, float& rx, float& ry) {
    __nv_bfloat162 h = __floats2bfloat162_rn(x, y);
    rx = x - __bfloat162float(h.x);
    ry = y - __bfloat162float(h.y);
    return *reinterpret_cast<unsigned*>(&h);
}
__device__ __forceinline__ unsigned pk(float x, float y) {
    __nv_bfloat162 h = __floats2bfloat162_rn(x, y);
    return *reinterpret_cast<unsigned*>(&h);
}
__device__ __forceinline__ int afrag_u(int r, int kp) {
    int kc = kp >> 3, tp = kp & 7;
    int m = r >> 4, rr = r & 15;
    int lane = ((rr & 7) << 2) | (tp & 3);
    int slot = ((tp >> 2) << 1) | (rr >> 3);
    return ((((kc * 3 + m) << 5) | lane) << 2) | slot;
}
__device__ __forceinline__ void mma_bf16(float* c, uint4 a, unsigned b0, unsigned b1) {
    asm volatile(
        "mma.sync.aligned.m16n8k16.row.col.f32.bf16.bf16.f32 "
        "{%0,%1,%2,%3}, {%4,%5,%6,%7}, {%8,%9}, {%0,%1,%2,%3};"
        : "+f"(c[0]), "+f"(c[1]), "+f"(c[2]), "+f"(c[3])
        : "r"(a.x), "r"(a.y), "r"(a.z), "r"(a.w), "r"(b0), "r"(b1));
}

__device__ __forceinline__ void grid_barrier() {
    __syncthreads();
    if (threadIdx.x == 0) {
        unsigned gen = *(volatile unsigned*)&g_bar_gen;
        __threadfence();
        unsigned t = atomicAdd(&g_bar_cnt, 1u);
        if (t == NB - 1) {
            *(volatile unsigned*)&g_bar_cnt = 0u;
            __threadfence();
            *(volatile unsigned*)&g_bar_gen = gen + 1u;
        } else {
            while (*(volatile unsigned*)&g_bar_gen == gen) { __nanosleep(32); }
        }
        __threadfence();
    }
    __syncthreads();
}

// ---------------- weight packing (once per launch) -------------------------------
__global__ void pack_wg(const float* __restrict__ Wi, const float* __restrict__ Wh)
{
    int idx = blockIdx.x * 256 + threadIdx.x;
    if (idx >= 384 * 96 * 32) return;
    int lane = idx & 31;
    int t2 = idx >> 5;
    int kc = t2 % 96, nt = t2 / 96;
    int n = nt * 8 + (lane >> 2);
    int k0 = kc * 16 + 2 * (lane & 3);
    const float* src; int kk;
    if (kc < 32) { src = Wi + n * Ez; kk = k0; }
    else         { src = Wh + n * Hz; kk = k0 - Ez; }
    float w00 = src[kk],     w01 = src[kk + 1];
    float w10 = src[kk + 8], w11 = src[kk + 9];
    float r00, r01, r10, r11;
    unsigned h0 = pk_hi(w00, w01, r00, r01);
    unsigned h1 = pk_hi(w10, w11, r10, r11);
    g_Wg_hi[idx] = make_uint2(h0, h1);
    g_Wg_lo[idx] = make_uint2(pk(r00, r01), pk(r10, r11));
}

__global__ void pack_wo(const float* __restrict__ Wo)
{
    int idx = blockIdx.x * 256 + threadIdx.x;
    if (idx >= 65 * 64 * 32) return;
    int lane = idx & 31;
    int kc = (idx >> 5) & 63, nt = idx >> 11;
    int n = nt * 8 + (lane >> 2);
    int k0 = kc * 16 + 2 * (lane & 3);
    float w00 = 0.f, w01 = 0.f, w10 = 0.f, w11 = 0.f;
    if (n < Ez + 1) {
        const float* src = Wo + n * Hz;
        w00 = src[k0]; w01 = src[k0 + 1]; w10 = src[k0 + 8]; w11 = src[k0 + 9];
    }
    float r00, r01, r10, r11;
    unsigned h0 = pk_hi(w00, w01, r00, r01);
    unsigned h1 = pk_hi(w10, w11, r10, r11);
    g_Wo_hi[idx] = make_uint2(h0, h1);
    g_Wo_lo[idx] = make_uint2(pk(r00, r01), pk(r10, r11));
}

// ---------------- init ------------------------------------------------------------

// emb_0 fp32 + emb_0 fragments + stops[:,0] = 0
__global__ void seed_kernel(const float* __restrict__ start, float* __restrict__ out)
{
    int idx = blockIdx.x * 256 + threadIdx.x;
    if (idx < Bz * Ez) g_emb[idx] = start[idx & (Ez - 1)];
    if (idx < Bz * 256) {
        int r = idx >> 8, kp = idx & 255;
        float x = start[2 * kp], y = start[2 * kp + 1];
        float rx, ry;
        ((unsigned*)g_eF_hi)[afrag_u(r, kp)] = pk_hi(x, y, rx, ry);
        ((unsigned*)g_eF_lo)[afrag_u(r, kp)] = pk(rx, ry);
    }
    if (idx < Bz) out[BTV + idx * Tz] = 0.f;
}

// fp32 48xN GEMM tile for init
struct __align__(16) SmemGemm { float As[16][52]; float Ws[16][68]; };

__device__ __forceinline__ void gemm48_tile(
    SmemGemm& sm, const float* __restrict__ A, int lda,
    const float* __restrict__ W, int ldw,
    float* __restrict__ C, int ldc, int N, int n0, int k0, int kc)
{
    int tid = threadIdx.x;
    int tx = tid & 15, ty = tid >> 4;
    float acc[3][4] = {{0,0,0,0},{0,0,0,0},{0,0,0,0}};
    for (int kk = 0; kk < kc; kk += 16) {
        if (tid < 192) {
            int r = tid >> 2, kq = tid & 3;
            float4 v = *(const float4*)(A + r * lda + k0 + kk + kq * 4);
            sm.As[kq*4+0][r] = v.x; sm.As[kq*4+1][r] = v.y;
            sm.As[kq*4+2][r] = v.z; sm.As[kq*4+3][r] = v.w;
        }
        {
            int n = tid >> 2, kq = tid & 3;
            int gn = n0 + n;
            float4 v = make_float4(0.f,0.f,0.f,0.f);
            if (gn < N) v = *(const float4*)(W + gn * ldw + k0 + kk + kq * 4);
            sm.Ws[kq*4+0][n] = v.x; sm.Ws[kq*4+1][n] = v.y;
            sm.Ws[kq*4+2][n] = v.z; sm.Ws[kq*4+3][n] = v.w;
        }
        __syncthreads();
        #pragma unroll
        for (int k = 0; k < 16; k++) {
            float a0 = sm.As[k][ty], a1 = sm.As[k][ty+16], a2 = sm.As[k][ty+32];
            float4 bv = *(const float4*)&sm.Ws[k][tx * 4];
            acc[0][0]+=a0*bv.x; acc[0][1]+=a0*bv.y; acc[0][2]+=a0*bv.z; acc[0][3]+=a0*bv.w;
            acc[1][0]+=a1*bv.x; acc[1][1]+=a1*bv.y; acc[1][2]+=a1*bv.z; acc[1][3]+=a1*bv.w;
            acc[2][0]+=a2*bv.x; acc[2][1]+=a2*bv.y; acc[2][2]+=a2*bv.z; acc[2][3]+=a2*bv.w;
        }
        __syncthreads();
    }
    #pragma unroll
    for (int i = 0; i < 3; i++) {
        int r = ty + i * 16;
        #pragma unroll
        for (int j = 0; j < 4; j++) {
            int n = n0 + tx * 4 + j;
            if (n < N) C[r * ldc + n] = acc[i][j];
        }
    }
}

// split-K init: partial C[48,4096] = [latent@W_lh^T | latent@Wp^T], K quarters
__global__ void init_part(const float* __restrict__ latent,
                          const float* __restrict__ W_lh, const float* __restrict__ Wp)
{
    __shared__ SmemGemm sm;
    int x = blockIdx.x, y = blockIdx.y;
    if (x < 16)
        gemm48_tile(sm, latent, Hz, W_lh, Hz, g_ipart[y], 4096, Hz, x * 64, y * 256, 256);
    else
        gemm48_tile(sm, latent, Hz, Wp, Hz, g_ipart[y] + 1024, 4096, G3, (x - 16) * 64, y * 256, 256);
}

// reduce init partials -> h0 (+frags) and peep
__global__ void init_reduce(const float* __restrict__ b_lh, const float* __restrict__ bp)
{
    int u = blockIdx.x * 256 + threadIdx.x;        // 48*1024 quad units
    if (u >= Bz * 1024) return;
    int r = u >> 10, q = u & 1023;
    int col = q * 4;
    float4 v = ld4(&g_ipart[0][r * 4096 + col]);
    #pragma unroll
    for (int p = 1; p < 4; p++) add4(v, ld4(&g_ipart[p][r * 4096 + col]));
    if (col < 1024) {
        float4 bb = ld4(b_lh + col);
        add4(v, bb);
        *(float4*)&g_h[0][r * Hz + col] = v;
        int kp = col >> 1;
        float rx, ry;
        unsigned u0 = pk_hi(v.x, v.y, rx, ry);
        ((unsigned*)g_hF_hi[0])[afrag_u(r, kp)] = u0;
        ((unsigned*)g_hF_lo[0])[afrag_u(r, kp)] = pk(rx, ry);
        unsigned u1 = pk_hi(v.z, v.w, rx, ry);
        ((unsigned*)g_hF_hi[0])[afrag_u(r, kp + 1)] = u1;
        ((unsigned*)g_hF_lo[0])[afrag_u(r, kp + 1)] = pk(rx, ry);
    } else {
        float4 bb = ld4(bp + (col - 1024));
        add4(v, bb);
        *(float4*)&g_peep[r * G3 + (col - 1024)] = v;
    }
}

// ---------------- persistent recurrence kernel ------------------------------------
// 128 blocks x 256 threads; per step: phase A (gates+GRU elementwise, 8 h-cols/block)
// -> grid barrier -> phase C (output projection + tanh/sigmoid, blocks 0..64)
// -> grid barrier.
__global__ void __launch_bounds__(256) recurrence_kernel(
    const float* __restrict__ bi, const float* __restrict__ bh,
    const float* __restrict__ bo, float* __restrict__ out)
{
    __shared__ float sm[8 * 4 * 48 * 8];           // 48 KB: A-phase [w][plane][48][8]
    int tid = threadIdx.x;
    int w = tid >> 5, lane = tid & 31;
    int b = blockIdx.x;
    int gID = lane >> 2, tig = lane & 3;
    int j0 = b * 8;

    for (int s = 0; s < Tz - 1; s++) {
        int cur = s & 1, nxt = cur ^ 1;

        // ---------- phase A: gate GEMM (3-pass bf16) + GRU elementwise ----------
        {
            const uint4* hFh = g_hF_hi[cur];
            const uint4* hFl = g_hF_lo[cur];
            float acc[4][3][4];                    // planes: r, i, n_i, n_h
            #pragma unroll
            for (int p = 0; p < 4; p++)
                #pragma unroll
                for (int m = 0; m < 3; m++)
                    #pragma unroll
                    for (int c = 0; c < 4; c++) acc[p][m][c] = 0.f;

            #pragma unroll 2
            for (int i = 0; i < 12; i++) {
                int kc = w + i * 8;                // stride-8: 4 emb-kc, 8 h-kc per warp
                bool isE = kc < 32;
                int kcp = isE ? kc : kc - 32;
                const uint4* Ah = isE ? g_eF_hi : hFh;
                const uint4* Al = isE ? g_eF_lo : hFl;
                uint4 ah[3], al[3];
                #pragma unroll
                for (int m = 0; m < 3; m++) {
                    ah[m] = Ah[(kcp * 3 + m) * 32 + lane];
                    al[m] = Al[(kcp * 3 + m) * 32 + lane];
                }
                #pragma unroll
                for (int g = 0; g < 3; g++) {
                    int widx = ((g * 128 + b) * 96 + kc) * 32 + lane;
                    uint2 bhv = g_Wg_hi[widx];
                    uint2 blv = g_Wg_lo[widx];
                    int pl = (g < 2) ? g : (isE ? 2 : 3);
                    #pragma unroll
                    for (int m = 0; m < 3; m++) {
                        mma_bf16(acc[pl][m], ah[m], bhv.x, bhv.y);
                        mma_bf16(acc[pl][m], al[m], bhv.x, bhv.y);
                        mma_bf16(acc[pl][m], ah[m], blv.x, blv.y);
                    }
                }
            }
            // write partials to smem
            #pragma unroll
            for (int p = 0; p < 4; p++)
                #pragma unroll
                for (int m = 0; m < 3; m++) {
                    int r0 = m * 16 + gID;
                    float* base = &sm[((w * 4 + p) * 48) * 8];
                    *(float2*)&base[r0 * 8 + 2 * tig]       = make_float2(acc[p][m][0], acc[p][m][1]);
                    *(float2*)&base[(r0 + 8) * 8 + 2 * tig] = make_float2(acc[p][m][2], acc[p][m][3]);
                }
        }
        __syncthreads();

        // GRU elementwise for this block's 8 columns
        if (tid < 192) {
            int r = tid >> 2, jj = tid & 3;
            int jl = 2 * jj;
            float res[2];
            #pragma unroll
            for (int q = 0; q < 2; q++) {
                int c = jl + q, j = j0 + c;
                float sr = 0.f, si = 0.f, sni = 0.f, snh = 0.f;
                #pragma unroll
                for (int w8 = 0; w8 < 8; w8++) {
                    sr  += sm[((w8 * 4 + 0) * 48 + r) * 8 + c];
                    si  += sm[((w8 * 4 + 1) * 48 + r) * 8 + c];
                    sni += sm[((w8 * 4 + 2) * 48 + r) * 8 + c];
                    snh += sm[((w8 * 4 + 3) * 48 + r) * 8 + c];
                }
                float gr = sr + bi[j] + bh[j] + g_peep[r * G3 + j];
                float gi = si + bi[Hz + j] + bh[Hz + j] + g_peep[r * G3 + Hz + j];
                float ti = sni + bi[2 * Hz + j] + g_peep[r * G3 + 2 * Hz + j];
                float th = snh + bh[2 * Hz + j];
                float rg = sigmoidf_(gr), zg = sigmoidf_(gi);
                float n = tanhf(ti + rg * th);
                float hp = g_h[cur][r * Hz + j];
                res[q] = n + zg * (hp - n);
            }
            *(float2*)&g_h[nxt][r * Hz + j0 + jl] = make_float2(res[0], res[1]);
            int kp = (j0 + jl) >> 1;
            float rx, ry;
            unsigned uh = pk_hi(res[0], res[1], rx, ry);
            ((unsigned*)g_hF_hi[nxt])[afrag_u(r, kp)] = uh;
            ((unsigned*)g_hF_lo[nxt])[afrag_u(r, kp)] = pk(rx, ry);
        }

        grid_barrier();

        // ---------- phase C: output projection + tanh/sigmoid (blocks 0..64) ----
        if (b < 65) {
            const uint4* Ah = g_hF_hi[nxt];
            const uint4* Al = g_hF_lo[nxt];
            float acc[3][4];
            #pragma unroll
            for (int m = 0; m < 3; m++)
                #pragma unroll
                for (int c = 0; c < 4; c++) acc[m][c] = 0.f;

            #pragma unroll 2
            for (int i = 0; i < 8; i++) {
                int kc = w * 8 + i;
                uint4 ah[3], al[3];
                #pragma unroll
                for (int m = 0; m < 3; m++) {
                    ah[m] = Ah[(kc * 3 + m) * 32 + lane];
                    al[m] = Al[(kc * 3 + m) * 32 + lane];
                }
                int widx = (b * 64 + kc) * 32 + lane;
                uint2 bhv = g_Wo_hi[widx];
                uint2 blv = g_Wo_lo[widx];
                #pragma unroll
                for (int m = 0; m < 3; m++) {
                    mma_bf16(acc[m], ah[m], bhv.x, bhv.y);
                    mma_bf16(acc[m], al[m], bhv.x, bhv.y);
                    mma_bf16(acc[m], ah[m], blv.x, blv.y);
                }
            }
            #pragma unroll
            for (int m = 0; m < 3; m++) {
                int r0 = m * 16 + gID;
                *(float2*)&sm[(w * 48 + r0) * 8 + 2 * tig]       = make_float2(acc[m][0], acc[m][1]);
                *(float2*)&sm[(w * 48 + r0 + 8) * 8 + 2 * tig]   = make_float2(acc[m][2], acc[m][3]);
            }
            __syncthreads();

            if (b < 64) {
                if (tid < 192) {
                    int r = tid >> 2, cp = tid & 3;
                    float e[2];
                    #pragma unroll
                    for (int q = 0; q < 2; q++) {
                        int c = 2 * cp + q, gc = b * 8 + c;
                        float v = bo[gc];
                        #pragma unroll
                        for (int w8 = 0; w8 < 8; w8++)
                            v += sm[(w8 * 48 + r) * 8 + c];
                        e[q] = tanhf(v);
                    }
                    int gc0 = b * 8 + 2 * cp;
                    *(float2*)&g_emb[((s + 1) * Bz + r) * Ez + gc0] = make_float2(e[0], e[1]);
                    int kp = gc0 >> 1;
                    float rx, ry;
                    unsigned uh = pk_hi(e[0], e[1], rx, ry);
                    ((unsigned*)g_eF_hi)[afrag_u(r, kp)] = uh;
                    ((unsigned*)g_eF_lo)[afrag_u(r, kp)] = pk(rx, ry);
                }
            } else {                                // b == 64: column 512 = stop
                if (tid < 192 && (tid & 3) == 0) {
                    int r = tid >> 2;
                    float v = bo[Ez];
                    #pragma unroll
                    for (int w8 = 0; w8 < 8; w8++)
                        v += sm[(w8 * 48 + r) * 8 + 0];
                    out[BTV + r * Tz + (s + 1)] = sigmoidf_(v);
                }
            }
            // smem reads complete before barrier's syncthreads below
        }

        grid_barrier();
    }
}

// ---------------- unembed: tf32 tensor-core GEMM (unchanged, proven) -------------
__global__ void __launch_bounds__(256) unembed_kernel(
    const float* __restrict__ Wu, const float* __restrict__ bu, float* __restrict__ out)
{
    __shared__ unsigned As[2][16][136];
    __shared__ unsigned Bs[2][16][136];

    int tid  = threadIdx.x;
    int warp = tid >> 5, lane = tid & 31;
    int wm = warp >> 2, wn = warp & 3;
    int m_warp = wm * 64, n_warp = wn * 32;
    int gID = lane >> 2, tig = lane & 3;

    const float* A  = g_emb + (size_t)blockIdx.y * 128 * Ez;
    const float* Bp = Wu    + (size_t)blockIdx.x * 128 * Ez;
    int r0 = tid >> 2, kq = tid & 3;

    float acc[4][4][4];
    #pragma unroll
    for (int mt = 0; mt < 4; mt++)
        #pragma unroll
        for (int nt = 0; nt < 4; nt++)
            #pragma unroll
            for (int c = 0; c < 4; c++) acc[mt][nt][c] = 0.f;

    {
        #pragma unroll
        for (int u = 0; u < 2; u++) {
            int r = r0 + u * 64;
            float4 va = *(const float4*)(A  + r * Ez + kq * 4);
            float4 vb = *(const float4*)(Bp + r * Ez + kq * 4);
            As[0][kq*4+0][r]=f2tf32(va.x); As[0][kq*4+1][r]=f2tf32(va.y);
            As[0][kq*4+2][r]=f2tf32(va.z); As[0][kq*4+3][r]=f2tf32(va.w);
            Bs[0][kq*4+0][r]=f2tf32(vb.x); Bs[0][kq*4+1][r]=f2tf32(vb.y);
            Bs[0][kq*4+2][r]=f2tf32(vb.z); Bs[0][kq*4+3][r]=f2tf32(vb.w);
        }
    }
    __syncthreads();

    const int NT = Ez / 16;
    for (int it = 0; it < NT; it++) {
        int cur = it & 1;
        float4 va[2], vb[2];
        bool more = (it + 1 < NT);
        if (more) {
            int kt = (it + 1) * 16;
            #pragma unroll
            for (int u = 0; u < 2; u++) {
                int r = r0 + u * 64;
                va[u] = *(const float4*)(A  + r * Ez + kt + kq * 4);
                vb[u] = *(const float4*)(Bp + r * Ez + kt + kq * 4);
            }
        }
        #pragma unroll
        for (int ks = 0; ks < 2; ks++) {
            int k0 = ks * 8;
            unsigned a[4][4];
            #pragma unroll
            for (int mt = 0; mt < 4; mt++) {
                int m0 = m_warp + mt * 16;
                a[mt][0] = As[cur][k0 + tig    ][m0 + gID    ];
                a[mt][1] = As[cur][k0 + tig    ][m0 + gID + 8];
                a[mt][2] = As[cur][k0 + tig + 4][m0 + gID    ];
                a[mt][3] = As[cur][k0 + tig + 4][m0 + gID + 8];
            }
            unsigned bfr[4][2];
            #pragma unroll
            for (int nt = 0; nt < 4; nt++) {
                int n0 = n_warp + nt * 8;
                bfr[nt][0] = Bs[cur][k0 + tig    ][n0 + gID];
                bfr[nt][1] = Bs[cur][k0 + tig + 4][n0 + gID];
            }
            #pragma unroll
            for (int mt = 0; mt < 4; mt++)
                #pragma unroll
                for (int nt = 0; nt < 4; nt++) {
                    asm volatile(
                        "mma.sync.aligned.m16n8k8.row.col.f32.tf32.tf32.f32 "
                        "{%0,%1,%2,%3}, {%4,%5,%6,%7}, {%8,%9}, {%0,%1,%2,%3};"
                        : "+f"(acc[mt][nt][0]), "+f"(acc[mt][nt][1]),
                          "+f"(acc[mt][nt][2]), "+f"(acc[mt][nt][3])
                        : "r"(a[mt][0]), "r"(a[mt][1]), "r"(a[mt][2]), "r"(a[mt][3]),
                          "r"(bfr[nt][0]), "r"(bfr[nt][1]));
                }
        }
        if (more) {
            int nxt = cur ^ 1;
            #pragma unroll
            for (int u = 0; u < 2; u++) {
                int r = r0 + u * 64;
                As[nxt][kq*4+0][r]=f2tf32(va[u].x); As[nxt][kq*4+1][r]=f2tf32(va[u].y);
                As[nxt][kq*4+2][r]=f2tf32(va[u].z); As[nxt][kq*4+3][r]=f2tf32(va[u].w);
                Bs[nxt][kq*4+0][r]=f2tf32(vb[u].x); Bs[nxt][kq*4+1][r]=f2tf32(vb[u].y);
                Bs[nxt][kq*4+2][r]=f2tf32(vb[u].z); Bs[nxt][kq*4+3][r]=f2tf32(vb[u].w);
            }
            __syncthreads();
        }
    }

    #pragma unroll
    for (int nt = 0; nt < 4; nt++) {
        int col = blockIdx.x * 128 + n_warp + nt * 8 + 2 * tig;
        float bv0 = bu[col], bv1 = bu[col + 1];
        #pragma unroll
        for (int mt = 0; mt < 4; mt++) {
            int m_lo = blockIdx.y * 128 + m_warp + mt * 16 + gID;
            #pragma unroll
            for (int half = 0; half < 2; half++) {
                int m = m_lo + half * 8;
                int t = m / Bz, bb = m % Bz;
                float* dst = out + (size_t)bb * (Tz * Vz) + (size_t)t * Vz + col;
                *(float2*)dst = make_float2(acc[mt][nt][half*2+0] + bv0,
                                            acc[mt][nt][half*2+1] + bv1);
            }
        }
    }
}

// ---------------- host -----------------------------------------------------------
extern "C" void kernel_launch(void* const* d_in, const int* in_sizes, int n_in,
                              void* d_out, int out_size)
{
    const float* latent = (const float*)d_in[1];
    const float* Wi     = (const float*)d_in[2];
    const float* bi     = (const float*)d_in[3];
    const float* Wh     = (const float*)d_in[4];
    const float* bh     = (const float*)d_in[5];
    const float* Wp     = (const float*)d_in[6];
    const float* bp     = (const float*)d_in[7];
    const float* W_lh   = (const float*)d_in[8];
    const float* b_lh   = (const float*)d_in[9];
    const float* Wo     = (const float*)d_in[10];
    const float* bo     = (const float*)d_in[11];
    const float* Wu     = (const float*)d_in[12];
    const float* bu     = (const float*)d_in[13];
    const float* start  = (const float*)d_in[14];
    float* out = (float*)d_out;

    pack_wg<<<4608, 256>>>(Wi, Wh);
    pack_wo<<<520, 256>>>(Wo);
    seed_kernel<<<96, 256>>>(start, out);
    init_part<<<dim3(64, 4), 256>>>(latent, W_lh, Wp);
    init_reduce<<<192, 256>>>(b_lh, bp);

    recurrence_kernel<<<NB, 256>>>(bi, bh, bo, out);

    unembed_kernel<<<dim3(Vz / 128, (Tz * Bz) / 128), 256>>>(Wu, bu, out);
}

// round 9
// speedup vs baseline: 2.1966x; 1.2134x over previous
#include <cuda_runtime.h>
#include <cuda_bf16.h>
#include <cuda_fp16.h>
#include <math.h>

#define Bz  48
#define Ez  512
#define Hz  1024
#define Vz  32000
#define Tz  64
#define G3  3072
#define BTV (Bz*Tz*Vz)
#define NB  128            // persistent blocks

// ---------------- scratch (static device memory) --------------------------------
__device__ float g_emb[Tz * Bz * Ez];          // emb_t fp32 (unembed input)
__device__ float g_h[2][Bz * Hz];              // hidden fp32 ping-pong
__device__ float g_peep[Bz * G3];
__device__ float g_ipart[4][Bz * 4096];        // init split-K partials (h0 | peep)

// packed weights: bf16 hi/lo in B-fragment order, uint2 {b0,b1} per lane
__device__ uint2 g_Wg_hi[384 * 96 * 32];       // [Wi|Wh] 3072x1536
__device__ uint2 g_Wg_lo[384 * 96 * 32];
__device__ uint2 g_Wo_hi[65 * 64 * 32];        // Wo 513x1024 (padded to 520 rows)
__device__ uint2 g_Wo_lo[65 * 64 * 32];

// activation A-fragments (uint4 per (kchunk, mtile, lane))
__device__ uint4 g_eF_hi[32 * 3 * 32];         // emb (K=512)
__device__ uint4 g_eF_lo[32 * 3 * 32];
__device__ uint4 g_hF_hi[2][64 * 3 * 32];      // h (K=1024), ping-pong
__device__ uint4 g_hF_lo[2][64 * 3 * 32];

// grid barrier state (zero-init; count returns to 0 each use -> graph-replay safe)
__device__ unsigned g_bar_cnt;
__device__ unsigned g_bar_gen;

__device__ __forceinline__ float sigmoidf_(float x) { return 1.f / (1.f + expf(-x)); }

__device__ __forceinline__ float4 ld4(const float* p) { return *(const float4*)p; }
__device__ __forceinline__ void add4(float4& a, float4 b) {
    a.x += b.x; a.y += b.y; a.z += b.z; a.w += b.w;
}
__device__ __forceinline__ unsigned pk_hi(float x, float y, float& rx, float& ry) {
    __nv_bfloat162 h = __floats2bfloat162_rn(x, y);
    rx = x - __bfloat162float(h.x);
    ry = y - __bfloat162float(h.y);
    return *reinterpret_cast<unsigned*>(&h);
}
__device__ __forceinline__ unsigned pk(float x, float y) {
    __nv_bfloat162 h = __floats2bfloat162_rn(x, y);
    return *reinterpret_cast<unsigned*>(&h);
}
__device__ __forceinline__ unsigned pkh(float x, float y) {
    __half2 h = __floats2half2_rn(x, y);
    return *reinterpret_cast<unsigned*>(&h);
}
__device__ __forceinline__ int afrag_u(int r, int kp) {
    int kc = kp >> 3, tp = kp & 7;
    int m = r >> 4, rr = r & 15;
    int lane = ((rr & 7) << 2) | (tp & 3);
    int slot = ((tp >> 2) << 1) | (rr >> 3);
    return ((((kc * 3 + m) << 5) | lane) << 2) | slot;
}
__device__ __forceinline__ void mma_bf16(float* c, uint4 a, unsigned b0, unsigned b1) {
    asm volatile(
        "mma.sync.aligned.m16n8k16.row.col.f32.bf16.bf16.f32 "
        "{%0,%1,%2,%3}, {%4,%5,%6,%7}, {%8,%9}, {%0,%1,%2,%3};"
        : "+f"(c[0]), "+f"(c[1]), "+f"(c[2]), "+f"(c[3])
        : "r"(a.x), "r"(a.y), "r"(a.z), "r"(a.w), "r"(b0), "r"(b1));
}
__device__ __forceinline__ void mma_fp16(float* c, unsigned a0, unsigned a1,
                                         unsigned a2, unsigned a3,
                                         unsigned b0, unsigned b1) {
    asm volatile(
        "mma.sync.aligned.m16n8k16.row.col.f32.f16.f16.f32 "
        "{%0,%1,%2,%3}, {%4,%5,%6,%7}, {%8,%9}, {%0,%1,%2,%3};"
        : "+f"(c[0]), "+f"(c[1]), "+f"(c[2]), "+f"(c[3])
        : "r"(a0), "r"(a1), "r"(a2), "r"(a3), "r"(b0), "r"(b1));
}

__device__ __forceinline__ void grid_barrier() {
    __syncthreads();
    if (threadIdx.x == 0) {
        unsigned gen = *(volatile unsigned*)&g_bar_gen;
        __threadfence();
        unsigned t = atomicAdd(&g_bar_cnt, 1u);
        if (t == NB - 1) {
            *(volatile unsigned*)&g_bar_cnt = 0u;
            __threadfence();
            *(volatile unsigned*)&g_bar_gen = gen + 1u;
        } else {
            while (*(volatile unsigned*)&g_bar_gen == gen) { __nanosleep(32); }
        }
        __threadfence();
    }
    __syncthreads();
}

// ---------------- weight packing (once per launch) -------------------------------
__global__ void pack_wg(const float* __restrict__ Wi, const float* __restrict__ Wh)
{
    int idx = blockIdx.x * 256 + threadIdx.x;
    if (idx >= 384 * 96 * 32) return;
    int lane = idx & 31;
    int t2 = idx >> 5;
    int kc = t2 % 96, nt = t2 / 96;
    int n = nt * 8 + (lane >> 2);
    int k0 = kc * 16 + 2 * (lane & 3);
    const float* src; int kk;
    if (kc < 32) { src = Wi + n * Ez; kk = k0; }
    else         { src = Wh + n * Hz; kk = k0 - Ez; }
    float w00 = src[kk],     w01 = src[kk + 1];
    float w10 = src[kk + 8], w11 = src[kk + 9];
    float r00, r01, r10, r11;
    unsigned h0 = pk_hi(w00, w01, r00, r01);
    unsigned h1 = pk_hi(w10, w11, r10, r11);
    g_Wg_hi[idx] = make_uint2(h0, h1);
    g_Wg_lo[idx] = make_uint2(pk(r00, r01), pk(r10, r11));
}

__global__ void pack_wo(const float* __restrict__ Wo)
{
    int idx = blockIdx.x * 256 + threadIdx.x;
    if (idx >= 65 * 64 * 32) return;
    int lane = idx & 31;
    int kc = (idx >> 5) & 63, nt = idx >> 11;
    int n = nt * 8 + (lane >> 2);
    int k0 = kc * 16 + 2 * (lane & 3);
    float w00 = 0.f, w01 = 0.f, w10 = 0.f, w11 = 0.f;
    if (n < Ez + 1) {
        const float* src = Wo + n * Hz;
        w00 = src[k0]; w01 = src[k0 + 1]; w10 = src[k0 + 8]; w11 = src[k0 + 9];
    }
    float r00, r01, r10, r11;
    unsigned h0 = pk_hi(w00, w01, r00, r01);
    unsigned h1 = pk_hi(w10, w11, r10, r11);
    g_Wo_hi[idx] = make_uint2(h0, h1);
    g_Wo_lo[idx] = make_uint2(pk(r00, r01), pk(r10, r11));
}

// ---------------- init ------------------------------------------------------------

// emb_0 fp32 + emb_0 fragments + stops[:,0] = 0
__global__ void seed_kernel(const float* __restrict__ start, float* __restrict__ out)
{
    int idx = blockIdx.x * 256 + threadIdx.x;
    if (idx < Bz * Ez) g_emb[idx] = start[idx & (Ez - 1)];
    if (idx < Bz * 256) {
        int r = idx >> 8, kp = idx & 255;
        float x = start[2 * kp], y = start[2 * kp + 1];
        float rx, ry;
        ((unsigned*)g_eF_hi)[afrag_u(r, kp)] = pk_hi(x, y, rx, ry);
        ((unsigned*)g_eF_lo)[afrag_u(r, kp)] = pk(rx, ry);
    }
    if (idx < Bz) out[BTV + idx * Tz] = 0.f;
}

// fp32 48xN GEMM tile for init
struct __align__(16) SmemGemm { float As[16][52]; float Ws[16][68]; };

__device__ __forceinline__ void gemm48_tile(
    SmemGemm& sm, const float* __restrict__ A, int lda,
    const float* __restrict__ W, int ldw,
    float* __restrict__ C, int ldc, int N, int n0, int k0, int kc)
{
    int tid = threadIdx.x;
    int tx = tid & 15, ty = tid >> 4;
    float acc[3][4] = {{0,0,0,0},{0,0,0,0},{0,0,0,0}};
    for (int kk = 0; kk < kc; kk += 16) {
        if (tid < 192) {
            int r = tid >> 2, kq = tid & 3;
            float4 v = *(const float4*)(A + r * lda + k0 + kk + kq * 4);
            sm.As[kq*4+0][r] = v.x; sm.As[kq*4+1][r] = v.y;
            sm.As[kq*4+2][r] = v.z; sm.As[kq*4+3][r] = v.w;
        }
        {
            int n = tid >> 2, kq = tid & 3;
            int gn = n0 + n;
            float4 v = make_float4(0.f,0.f,0.f,0.f);
            if (gn < N) v = *(const float4*)(W + gn * ldw + k0 + kk + kq * 4);
            sm.Ws[kq*4+0][n] = v.x; sm.Ws[kq*4+1][n] = v.y;
            sm.Ws[kq*4+2][n] = v.z; sm.Ws[kq*4+3][n] = v.w;
        }
        __syncthreads();
        #pragma unroll
        for (int k = 0; k < 16; k++) {
            float a0 = sm.As[k][ty], a1 = sm.As[k][ty+16], a2 = sm.As[k][ty+32];
            float4 bv = *(const float4*)&sm.Ws[k][tx * 4];
            acc[0][0]+=a0*bv.x; acc[0][1]+=a0*bv.y; acc[0][2]+=a0*bv.z; acc[0][3]+=a0*bv.w;
            acc[1][0]+=a1*bv.x; acc[1][1]+=a1*bv.y; acc[1][2]+=a1*bv.z; acc[1][3]+=a1*bv.w;
            acc[2][0]+=a2*bv.x; acc[2][1]+=a2*bv.y; acc[2][2]+=a2*bv.z; acc[2][3]+=a2*bv.w;
        }
        __syncthreads();
    }
    #pragma unroll
    for (int i = 0; i < 3; i++) {
        int r = ty + i * 16;
        #pragma unroll
        for (int j = 0; j < 4; j++) {
            int n = n0 + tx * 4 + j;
            if (n < N) C[r * ldc + n] = acc[i][j];
        }
    }
}

// split-K init: partial C[48,4096] = [latent@W_lh^T | latent@Wp^T], K quarters
__global__ void init_part(const float* __restrict__ latent,
                          const float* __restrict__ W_lh, const float* __restrict__ Wp)
{
    __shared__ SmemGemm sm;
    int x = blockIdx.x, y = blockIdx.y;
    if (x < 16)
        gemm48_tile(sm, latent, Hz, W_lh, Hz, g_ipart[y], 4096, Hz, x * 64, y * 256, 256);
    else
        gemm48_tile(sm, latent, Hz, Wp, Hz, g_ipart[y] + 1024, 4096, G3, (x - 16) * 64, y * 256, 256);
}

// reduce init partials -> h0 (+frags) and peep
__global__ void init_reduce(const float* __restrict__ b_lh, const float* __restrict__ bp)
{
    int u = blockIdx.x * 256 + threadIdx.x;
    if (u >= Bz * 1024) return;
    int r = u >> 10, q = u & 1023;
    int col = q * 4;
    float4 v = ld4(&g_ipart[0][r * 4096 + col]);
    #pragma unroll
    for (int p = 1; p < 4; p++) add4(v, ld4(&g_ipart[p][r * 4096 + col]));
    if (col < 1024) {
        float4 bb = ld4(b_lh + col);
        add4(v, bb);
        *(float4*)&g_h[0][r * Hz + col] = v;
        int kp = col >> 1;
        float rx, ry;
        unsigned u0 = pk_hi(v.x, v.y, rx, ry);
        ((unsigned*)g_hF_hi[0])[afrag_u(r, kp)] = u0;
        ((unsigned*)g_hF_lo[0])[afrag_u(r, kp)] = pk(rx, ry);
        unsigned u1 = pk_hi(v.z, v.w, rx, ry);
        ((unsigned*)g_hF_hi[0])[afrag_u(r, kp + 1)] = u1;
        ((unsigned*)g_hF_lo[0])[afrag_u(r, kp + 1)] = pk(rx, ry);
    } else {
        float4 bb = ld4(bp + (col - 1024));
        add4(v, bb);
        *(float4*)&g_peep[r * G3 + (col - 1024)] = v;
    }
}

// ---------------- persistent recurrence kernel (unchanged from R8) ----------------
__global__ void __launch_bounds__(256) recurrence_kernel(
    const float* __restrict__ bi, const float* __restrict__ bh,
    const float* __restrict__ bo, float* __restrict__ out)
{
    __shared__ float sm[8 * 4 * 48 * 8];
    int tid = threadIdx.x;
    int w = tid >> 5, lane = tid & 31;
    int b = blockIdx.x;
    int gID = lane >> 2, tig = lane & 3;
    int j0 = b * 8;

    for (int s = 0; s < Tz - 1; s++) {
        int cur = s & 1, nxt = cur ^ 1;

        // ---------- phase A: gate GEMM (3-pass bf16) + GRU elementwise ----------
        {
            const uint4* hFh = g_hF_hi[cur];
            const uint4* hFl = g_hF_lo[cur];
            float acc[4][3][4];
            #pragma unroll
            for (int p = 0; p < 4; p++)
                #pragma unroll
                for (int m = 0; m < 3; m++)
                    #pragma unroll
                    for (int c = 0; c < 4; c++) acc[p][m][c] = 0.f;

            #pragma unroll 2
            for (int i = 0; i < 12; i++) {
                int kc = w + i * 8;
                bool isE = kc < 32;
                int kcp = isE ? kc : kc - 32;
                const uint4* Ah = isE ? g_eF_hi : hFh;
                const uint4* Al = isE ? g_eF_lo : hFl;
                uint4 ah[3], al[3];
                #pragma unroll
                for (int m = 0; m < 3; m++) {
                    ah[m] = Ah[(kcp * 3 + m) * 32 + lane];
                    al[m] = Al[(kcp * 3 + m) * 32 + lane];
                }
                #pragma unroll
                for (int g = 0; g < 3; g++) {
                    int widx = ((g * 128 + b) * 96 + kc) * 32 + lane;
                    uint2 bhv = g_Wg_hi[widx];
                    uint2 blv = g_Wg_lo[widx];
                    int pl = (g < 2) ? g : (isE ? 2 : 3);
                    #pragma unroll
                    for (int m = 0; m < 3; m++) {
                        mma_bf16(acc[pl][m], ah[m], bhv.x, bhv.y);
                        mma_bf16(acc[pl][m], al[m], bhv.x, bhv.y);
                        mma_bf16(acc[pl][m], ah[m], blv.x, blv.y);
                    }
                }
            }
            #pragma unroll
            for (int p = 0; p < 4; p++)
                #pragma unroll
                for (int m = 0; m < 3; m++) {
                    int r0 = m * 16 + gID;
                    float* base = &sm[((w * 4 + p) * 48) * 8];
                    *(float2*)&base[r0 * 8 + 2 * tig]       = make_float2(acc[p][m][0], acc[p][m][1]);
                    *(float2*)&base[(r0 + 8) * 8 + 2 * tig] = make_float2(acc[p][m][2], acc[p][m][3]);
                }
        }
        __syncthreads();

        if (tid < 192) {
            int r = tid >> 2, jj = tid & 3;
            int jl = 2 * jj;
            float res[2];
            #pragma unroll
            for (int q = 0; q < 2; q++) {
                int c = jl + q, j = j0 + c;
                float sr = 0.f, si = 0.f, sni = 0.f, snh = 0.f;
                #pragma unroll
                for (int w8 = 0; w8 < 8; w8++) {
                    sr  += sm[((w8 * 4 + 0) * 48 + r) * 8 + c];
                    si  += sm[((w8 * 4 + 1) * 48 + r) * 8 + c];
                    sni += sm[((w8 * 4 + 2) * 48 + r) * 8 + c];
                    snh += sm[((w8 * 4 + 3) * 48 + r) * 8 + c];
                }
                float gr = sr + bi[j] + bh[j] + g_peep[r * G3 + j];
                float gi = si + bi[Hz + j] + bh[Hz + j] + g_peep[r * G3 + Hz + j];
                float ti = sni + bi[2 * Hz + j] + g_peep[r * G3 + 2 * Hz + j];
                float th = snh + bh[2 * Hz + j];
                float rg = sigmoidf_(gr), zg = sigmoidf_(gi);
                float n = tanhf(ti + rg * th);
                float hp = g_h[cur][r * Hz + j];
                res[q] = n + zg * (hp - n);
            }
            *(float2*)&g_h[nxt][r * Hz + j0 + jl] = make_float2(res[0], res[1]);
            int kp = (j0 + jl) >> 1;
            float rx, ry;
            unsigned uh = pk_hi(res[0], res[1], rx, ry);
            ((unsigned*)g_hF_hi[nxt])[afrag_u(r, kp)] = uh;
            ((unsigned*)g_hF_lo[nxt])[afrag_u(r, kp)] = pk(rx, ry);
        }

        grid_barrier();

        // ---------- phase C: output projection + tanh/sigmoid (blocks 0..64) ----
        if (b < 65) {
            const uint4* Ah = g_hF_hi[nxt];
            const uint4* Al = g_hF_lo[nxt];
            float acc[3][4];
            #pragma unroll
            for (int m = 0; m < 3; m++)
                #pragma unroll
                for (int c = 0; c < 4; c++) acc[m][c] = 0.f;

            #pragma unroll 2
            for (int i = 0; i < 8; i++) {
                int kc = w * 8 + i;
                uint4 ah[3], al[3];
                #pragma unroll
                for (int m = 0; m < 3; m++) {
                    ah[m] = Ah[(kc * 3 + m) * 32 + lane];
                    al[m] = Al[(kc * 3 + m) * 32 + lane];
                }
                int widx = (b * 64 + kc) * 32 + lane;
                uint2 bhv = g_Wo_hi[widx];
                uint2 blv = g_Wo_lo[widx];
                #pragma unroll
                for (int m = 0; m < 3; m++) {
                    mma_bf16(acc[m], ah[m], bhv.x, bhv.y);
                    mma_bf16(acc[m], al[m], bhv.x, bhv.y);
                    mma_bf16(acc[m], ah[m], blv.x, blv.y);
                }
            }
            #pragma unroll
            for (int m = 0; m < 3; m++) {
                int r0 = m * 16 + gID;
                *(float2*)&sm[(w * 48 + r0) * 8 + 2 * tig]       = make_float2(acc[m][0], acc[m][1]);
                *(float2*)&sm[(w * 48 + r0 + 8) * 8 + 2 * tig]   = make_float2(acc[m][2], acc[m][3]);
            }
            __syncthreads();

            if (b < 64) {
                if (tid < 192) {
                    int r = tid >> 2, cp = tid & 3;
                    float e[2];
                    #pragma unroll
                    for (int q = 0; q < 2; q++) {
                        int c = 2 * cp + q, gc = b * 8 + c;
                        float v = bo[gc];
                        #pragma unroll
                        for (int w8 = 0; w8 < 8; w8++)
                            v += sm[(w8 * 48 + r) * 8 + c];
                        e[q] = tanhf(v);
                    }
                    int gc0 = b * 8 + 2 * cp;
                    *(float2*)&g_emb[((s + 1) * Bz + r) * Ez + gc0] = make_float2(e[0], e[1]);
                    int kp = gc0 >> 1;
                    float rx, ry;
                    unsigned uh = pk_hi(e[0], e[1], rx, ry);
                    ((unsigned*)g_eF_hi)[afrag_u(r, kp)] = uh;
                    ((unsigned*)g_eF_lo)[afrag_u(r, kp)] = pk(rx, ry);
                }
            } else {
                if (tid < 192 && (tid & 3) == 0) {
                    int r = tid >> 2;
                    float v = bo[Ez];
                    #pragma unroll
                    for (int w8 = 0; w8 < 8; w8++)
                        v += sm[(w8 * 48 + r) * 8 + 0];
                    out[BTV + r * Tz + (s + 1)] = sigmoidf_(v);
                }
            }
        }

        grid_barrier();
    }
}

// ---------------- unembed: fp16 tensor-core GEMM ---------------------------------
// logits: (T*B=3072, E=512) @ Wu^T (V=32000) + bu -> out in (B,T,V) layout.
// Block 128x128, 8 warps (2x4), warp tile 64x32, mma.m16n8k16.f16 (fp32 accum).
// Smem [kpair][row] half2, pad 136 -> conflict-free. Double-buffered, BK=16.
__global__ void __launch_bounds__(256) unembed_kernel(
    const float* __restrict__ Wu, const float* __restrict__ bu, float* __restrict__ out)
{
    __shared__ unsigned As[2][8][136];
    __shared__ unsigned Bs[2][8][136];

    int tid  = threadIdx.x;
    int warp = tid >> 5, lane = tid & 31;
    int wm = warp >> 2, wn = warp & 3;
    int m_warp = wm * 64, n_warp = wn * 32;
    int gID = lane >> 2, tig = lane & 3;

    const float* A  = g_emb + (size_t)blockIdx.y * 128 * Ez;
    const float* Bp = Wu    + (size_t)blockIdx.x * 128 * Ez;
    int r0 = tid >> 2, kq = tid & 3;            // row 0..63 (+64), float4 seg 0..3

    float acc[4][4][4];
    #pragma unroll
    for (int mt = 0; mt < 4; mt++)
        #pragma unroll
        for (int nt = 0; nt < 4; nt++)
            #pragma unroll
            for (int c = 0; c < 4; c++) acc[mt][nt][c] = 0.f;

    // preload stage 0
    {
        #pragma unroll
        for (int u = 0; u < 2; u++) {
            int r = r0 + u * 64;
            float4 va = *(const float4*)(A  + r * Ez + kq * 4);
            float4 vb = *(const float4*)(Bp + r * Ez + kq * 4);
            As[0][2*kq  ][r] = pkh(va.x, va.y);
            As[0][2*kq+1][r] = pkh(va.z, va.w);
            Bs[0][2*kq  ][r] = pkh(vb.x, vb.y);
            Bs[0][2*kq+1][r] = pkh(vb.z, vb.w);
        }
    }
    __syncthreads();

    const int NT = Ez / 16;                     // 32 stages, one k16 mma step each
    for (int it = 0; it < NT; it++) {
        int cur = it & 1;
        float4 va[2], vb[2];
        bool more = (it + 1 < NT);
        if (more) {
            int kt = (it + 1) * 16;
            #pragma unroll
            for (int u = 0; u < 2; u++) {
                int r = r0 + u * 64;
                va[u] = *(const float4*)(A  + r * Ez + kt + kq * 4);
                vb[u] = *(const float4*)(Bp + r * Ez + kt + kq * 4);
            }
        }

        {
            unsigned a[4][4];
            #pragma unroll
            for (int mt = 0; mt < 4; mt++) {
                int m0 = m_warp + mt * 16;
                a[mt][0] = As[cur][tig    ][m0 + gID    ];
                a[mt][1] = As[cur][tig    ][m0 + gID + 8];
                a[mt][2] = As[cur][tig + 4][m0 + gID    ];
                a[mt][3] = As[cur][tig + 4][m0 + gID + 8];
            }
            unsigned bfr[4][2];
            #pragma unroll
            for (int nt = 0; nt < 4; nt++) {
                int n0 = n_warp + nt * 8;
                bfr[nt][0] = Bs[cur][tig    ][n0 + gID];
                bfr[nt][1] = Bs[cur][tig + 4][n0 + gID];
            }
            #pragma unroll
            for (int mt = 0; mt < 4; mt++)
                #pragma unroll
                for (int nt = 0; nt < 4; nt++)
                    mma_fp16(acc[mt][nt], a[mt][0], a[mt][1], a[mt][2], a[mt][3],
                             bfr[nt][0], bfr[nt][1]);
        }

        if (more) {
            int nxt = cur ^ 1;
            #pragma unroll
            for (int u = 0; u < 2; u++) {
                int r = r0 + u * 64;
                As[nxt][2*kq  ][r] = pkh(va[u].x, va[u].y);
                As[nxt][2*kq+1][r] = pkh(va[u].z, va[u].w);
                Bs[nxt][2*kq  ][r] = pkh(vb[u].x, vb[u].y);
                Bs[nxt][2*kq+1][r] = pkh(vb[u].z, vb[u].w);
            }
            __syncthreads();
        }
    }

    #pragma unroll
    for (int nt = 0; nt < 4; nt++) {
        int col = blockIdx.x * 128 + n_warp + nt * 8 + 2 * tig;
        float bv0 = bu[col], bv1 = bu[col + 1];
        #pragma unroll
        for (int mt = 0; mt < 4; mt++) {
            int m_lo = blockIdx.y * 128 + m_warp + mt * 16 + gID;
            #pragma unroll
            for (int half = 0; half < 2; half++) {
                int m = m_lo + half * 8;
                int t = m / Bz, bb = m % Bz;
                float* dst = out + (size_t)bb * (Tz * Vz) + (size_t)t * Vz + col;
                *(float2*)dst = make_float2(acc[mt][nt][half*2+0] + bv0,
                                            acc[mt][nt][half*2+1] + bv1);
            }
        }
    }
}

// ---------------- host -----------------------------------------------------------
extern "C" void kernel_launch(void* const* d_in, const int* in_sizes, int n_in,
                              void* d_out, int out_size)
{
    const float* latent = (const float*)d_in[1];
    const float* Wi     = (const float*)d_in[2];
    const float* bi     = (const float*)d_in[3];
    const float* Wh     = (const float*)d_in[4];
    const float* bh     = (const float*)d_in[5];
    const float* Wp     = (const float*)d_in[6];
    const float* bp     = (const float*)d_in[7];
    const float* W_lh   = (const float*)d_in[8];
    const float* b_lh   = (const float*)d_in[9];
    const float* Wo     = (const float*)d_in[10];
    const float* bo     = (const float*)d_in[11];
    const float* Wu     = (const float*)d_in[12];
    const float* bu     = (const float*)d_in[13];
    const float* start  = (const float*)d_in[14];
    float* out = (float*)d_out;

    pack_wg<<<4608, 256>>>(Wi, Wh);
    pack_wo<<<520, 256>>>(Wo);
    seed_kernel<<<96, 256>>>(start, out);
    init_part<<<dim3(64, 4), 256>>>(latent, W_lh, Wp);
    init_reduce<<<192, 256>>>(b_lh, bp);

    recurrence_kernel<<<NB, 256>>>(bi, bh, bo, out);

    unembed_kernel<<<dim3(Vz / 128, (Tz * Bz) / 128), 256>>>(Wu, bu, out);
}